// round 8
// baseline (speedup 1.0000x reference)
#include <cuda_runtime.h>
#include <cuda_bf16.h>
#include <cstdint>
#include <math.h>

#define BATCH 256
#define NHEAD 16
#define HDIM  128
#define HID   2048        // NHEAD * HDIM
#define N3    6144        // 3 * HID

// Scratch: activated gates and projections, [B, HID] each
__device__ __align__(16) float g_i[BATCH * HID];
__device__ __align__(16) float g_f[BATCH * HID];
__device__ __align__(16) float g_o[BATCH * HID];
__device__ __align__(16) float g_q[BATCH * HID];
__device__ __align__(16) float g_k[BATCH * HID];
__device__ __align__(16) float g_v[BATCH * HID];

// Split-precision scratch (bf16 hi/lo)
__device__ __align__(16) __nv_bfloat16 s_xh[BATCH * HID];
__device__ __align__(16) __nv_bfloat16 s_xl[BATCH * HID];
__device__ __align__(16) __nv_bfloat16 s_wh[(size_t)N3 * HID];   // W_i^T [6144,2048]
__device__ __align__(16) __nv_bfloat16 s_wl[(size_t)N3 * HID];
__device__ __align__(16) __nv_bfloat16 s_wqh[NHEAD * 384 * HDIM]; // W_qkv^T [h][384][128]
__device__ __align__(16) __nv_bfloat16 s_wql[NHEAD * 384 * HDIM];

// ---------------------------------------------------------------------------
// Split x -> bf16 hi/lo
// ---------------------------------------------------------------------------
__global__ __launch_bounds__(256) void split_x_kernel(const float* __restrict__ x)
{
    int idx = blockIdx.x * 256 + threadIdx.x;
    float v = x[idx];
    __nv_bfloat16 hi = __float2bfloat16(v);
    float lo = v - __bfloat162float(hi);
    s_xh[idx] = hi;
    s_xl[idx] = __float2bfloat16(lo);
}

// ---------------------------------------------------------------------------
// Split + transpose W_i [2048,6144] -> Wt hi/lo [6144,2048]
// ---------------------------------------------------------------------------
__global__ __launch_bounds__(256) void splitT_w_kernel(const float* __restrict__ W)
{
    __shared__ float tile[32][33];
    const int n0 = blockIdx.x * 32;
    const int k0 = blockIdx.y * 32;
    const int tx = threadIdx.x & 31;
    const int ty = threadIdx.x >> 5;   // 0..7

    #pragma unroll
    for (int j = 0; j < 4; j++)
        tile[ty + j * 8][tx] = W[(size_t)(k0 + ty + j * 8) * N3 + n0 + tx];
    __syncthreads();

    #pragma unroll
    for (int j = 0; j < 4; j++) {
        float v = tile[tx][ty + j * 8];
        __nv_bfloat16 hi = __float2bfloat16(v);
        float lo = v - __bfloat162float(hi);
        size_t o = (size_t)(n0 + ty + j * 8) * HID + k0 + tx;
        s_wh[o] = hi;
        s_wl[o] = __float2bfloat16(lo);
    }
}

// ---------------------------------------------------------------------------
// Split + transpose W_qkv [h][128][384] -> [h][384][128] hi/lo
// ---------------------------------------------------------------------------
__global__ __launch_bounds__(256) void splitT_wq_kernel(const float* __restrict__ Wq)
{
    __shared__ float tile[32][33];
    const int n0 = blockIdx.x * 32;     // 0..352
    const int k0 = blockIdx.y * 32;     // 0..96
    const int h  = blockIdx.z;
    const int tx = threadIdx.x & 31;
    const int ty = threadIdx.x >> 5;

    #pragma unroll
    for (int j = 0; j < 4; j++)
        tile[ty + j * 8][tx] = Wq[((size_t)h * HDIM + k0 + ty + j * 8) * 384 + n0 + tx];
    __syncthreads();

    #pragma unroll
    for (int j = 0; j < 4; j++) {
        float v = tile[tx][ty + j * 8];
        __nv_bfloat16 hi = __float2bfloat16(v);
        float lo = v - __bfloat162float(hi);
        size_t o = ((size_t)h * 384 + n0 + ty + j * 8) * HDIM + k0 + tx;
        s_wqh[o] = hi;
        s_wql[o] = __float2bfloat16(lo);
    }
}

// ---------------------------------------------------------------------------
// PTX helpers (sm_80-compatible: cp.async + ldmatrix + mma.sync)
// ---------------------------------------------------------------------------
__device__ __forceinline__ void cp_async16(uint32_t dst, const void* src) {
    asm volatile("cp.async.cg.shared.global [%0], [%1], 16;"
                 :: "r"(dst), "l"(src));
}
__device__ __forceinline__ void cp_commit() {
    asm volatile("cp.async.commit_group;");
}

__device__ __forceinline__ void ldm_x4(uint32_t* r, uint32_t addr) {
    asm volatile("ldmatrix.sync.aligned.m8n8.x4.shared.b16 {%0,%1,%2,%3}, [%4];"
                 : "=r"(r[0]), "=r"(r[1]), "=r"(r[2]), "=r"(r[3]) : "r"(addr));
}

__device__ __forceinline__ void mma16816(float* c, const uint32_t* a, const uint32_t* b) {
    asm volatile(
        "mma.sync.aligned.m16n8k16.row.col.f32.bf16.bf16.f32 "
        "{%0,%1,%2,%3}, {%4,%5,%6,%7}, {%8,%9}, {%0,%1,%2,%3};"
        : "+f"(c[0]), "+f"(c[1]), "+f"(c[2]), "+f"(c[3])
        : "r"(a[0]), "r"(a[1]), "r"(a[2]), "r"(a[3]), "r"(b[0]), "r"(b[1]));
}

#define SST 72                    // bf16 elems per smem row (144B = 9*16B)

// ===========================================================================
// Gates GEMM: D = Xh@Wh^T + Xl@Wh^T + Xh@Wl^T  (bf16x3 split precision)
// CTA tile 64x96, 256 threads, 8 warps 4Mx2N, warp tile 16x48.
// Grid 64x4 = 256 CTAs, 2 CTAs/SM co-resident -> 4 warps/SMSP.
// BK=64, 3-stage cp.async ring (69KB smem).
// ===========================================================================
#define GA_STAGE (64 * SST * 2)       // 9216
#define GB_STAGE (96 * SST * 2)       // 13824
#define G_STAGE (GA_STAGE + GB_STAGE) // 23040
#define G_NSTAGES 96
#define G_DSMEM (3 * G_STAGE)         // 69120

__global__ __launch_bounds__(256, 2) void gates_mma_kernel(const float* __restrict__ bias)
{
    extern __shared__ __nv_bfloat16 smem[];

    const int tid = threadIdx.x;
    const int lane = tid & 31;
    const int wid = tid >> 5;
    const int warp_m = (wid & 3) * 16;     // 0,16,32,48
    const int warp_n = (wid >> 2) * 48;    // 0,48
    const int n0 = blockIdx.x * 96;
    const int m0 = blockIdx.y * 64;

    const int r_s = tid >> 3;              // 0..31
    const int seg = tid & 7;

    const uint32_t sbase = (uint32_t)__cvta_generic_to_shared(smem);

    float c[6][4];
    #pragma unroll
    for (int j = 0; j < 6; j++)
        #pragma unroll
        for (int q = 0; q < 4; q++) c[j][q] = 0.0f;

    auto load_stage = [&](int s) {
        const int term = s >> 5;
        const int k0 = (s & 31) << 6;
        const __nv_bfloat16* Ap = (term == 1) ? s_xl : s_xh;
        const __nv_bfloat16* Bp = (term == 2) ? s_wl : s_wh;
        const uint32_t buf = sbase + (uint32_t)(s % 3) * G_STAGE;
        #pragma unroll
        for (int h = 0; h < 2; h++) {
            const int row = r_s + h * 32;
            cp_async16(buf + (uint32_t)(row * 144 + seg * 16),
                       Ap + (size_t)(m0 + row) * HID + k0 + seg * 8);
        }
        #pragma unroll
        for (int h = 0; h < 3; h++) {
            const int row = r_s + h * 32;
            cp_async16(buf + GA_STAGE + (uint32_t)(row * 144 + seg * 16),
                       Bp + (size_t)(n0 + row) * HID + k0 + seg * 8);
        }
    };

    auto load_frags = [&](uint32_t Ab, uint32_t Bb, int kk,
                          uint32_t af[4], uint32_t bf[6][2]) {
        {
            const int row = warp_m + (lane & 15);
            const int col = kk + ((lane >> 4) << 3);
            ldm_x4(af, Ab + (uint32_t)(row * SST + col) * 2);
        }
        const int g = lane >> 3;
        #pragma unroll
        for (int nb = 0; nb < 3; nb++) {
            const int nrow = warp_n + nb * 16 + ((g >> 1) << 3) + (lane & 7);
            const int col = kk + ((g & 1) << 3);
            uint32_t rr[4];
            ldm_x4(rr, Bb + (uint32_t)(nrow * SST + col) * 2);
            bf[nb * 2 + 0][0] = rr[0]; bf[nb * 2 + 0][1] = rr[1];
            bf[nb * 2 + 1][0] = rr[2]; bf[nb * 2 + 1][1] = rr[3];
        }
    };

    load_stage(0); cp_commit();
    load_stage(1); cp_commit();

    uint32_t af[2][4];
    uint32_t bf[2][6][2];

    for (int s = 0; s < G_NSTAGES; ++s) {
        asm volatile("cp.async.wait_group 1;");
        __syncthreads();
        if (s + 2 < G_NSTAGES) load_stage(s + 2);
        cp_commit();

        const uint32_t Ab = sbase + (uint32_t)(s % 3) * G_STAGE;
        const uint32_t Bb = Ab + GA_STAGE;

        load_frags(Ab, Bb, 0, af[0], bf[0]);
        #pragma unroll
        for (int ki = 0; ki < 4; ki++) {
            const int cur = ki & 1;
            if (ki < 3)
                load_frags(Ab, Bb, (ki + 1) * 16, af[cur ^ 1], bf[cur ^ 1]);
            #pragma unroll
            for (int j = 0; j < 6; j++)
                mma16816(c[j], af[cur], bf[cur][j]);
        }
    }

    // Epilogue: per-column gate class (pair never straddles a class boundary)
    const int mrow = m0 + warp_m + (lane >> 2);
    #pragma unroll
    for (int j = 0; j < 6; j++) {
        const int col = n0 + warp_n + j * 8 + ((lane & 3) << 1);
        const int cls = col >> 11;          // 0:i 1:f 2:o
        float* outp = (cls == 0) ? g_i : ((cls == 1) ? g_f : g_o);
        const int cb = col & 2047;
        const float b0 = bias[col], b1 = bias[col + 1];
        float t0 = c[j][0] + b0, t1 = c[j][1] + b1;
        float t2 = c[j][2] + b0, t3 = c[j][3] + b1;
        float2 v0, v1;
        if (cls == 2) {
            v0.x = 1.0f / (1.0f + expf(-t0));
            v0.y = 1.0f / (1.0f + expf(-t1));
            v1.x = 1.0f / (1.0f + expf(-t2));
            v1.y = 1.0f / (1.0f + expf(-t3));
        } else {
            v0.x = expf(t0); v0.y = expf(t1);
            v1.x = expf(t2); v1.y = expf(t3);
        }
        *(float2*)(outp + (size_t)mrow * HID + cb) = v0;
        *(float2*)(outp + (size_t)(mrow + 8) * HID + cb) = v1;
    }
}

// ===========================================================================
// QKV GEMM (per-head, bf16x3): M=256, N=384, K=128 per head.
// CTA tile 128x128, grid (3, 2, 16) = 96 CTAs, 6 stages of BK=64.
// ===========================================================================
#define Q_STAGE (2 * 128 * SST * 2)   // 36864 (A + B, both 128 rows)
#define Q_NSTAGES 6
#define Q_DSMEM (3 * Q_STAGE)         // 110592

__global__ __launch_bounds__(256, 1) void qkv_mma_kernel(const float* __restrict__ bq)
{
    extern __shared__ __nv_bfloat16 smem[];

    const int tid = threadIdx.x;
    const int lane = tid & 31;
    const int wid = tid >> 5;
    const int warp_m = (wid & 3) * 32;
    const int warp_n = (wid >> 2) * 64;
    const int n0 = blockIdx.x * 128;       // 0,128,256 (of 384)
    const int m0 = blockIdx.y * 128;
    const int head = blockIdx.z;

    const int r_s = tid >> 3;
    const int seg = tid & 7;

    const uint32_t sbase = (uint32_t)__cvta_generic_to_shared(smem);

    float c[2][8][4];
    #pragma unroll
    for (int i = 0; i < 2; i++)
        #pragma unroll
        for (int j = 0; j < 8; j++)
            #pragma unroll
            for (int q = 0; q < 4; q++) c[i][j][q] = 0.0f;

    auto load_stage = [&](int s) {
        const int term = s >> 1;           // 0,1,2
        const int k0 = (s & 1) << 6;
        const __nv_bfloat16* Ap = (term == 1) ? s_xl : s_xh;
        const __nv_bfloat16* Bp = (term == 2) ? s_wql : s_wqh;
        const uint32_t buf = sbase + (uint32_t)(s % 3) * Q_STAGE;
        #pragma unroll
        for (int h = 0; h < 4; h++) {
            const int row = r_s + h * 32;
            const uint32_t doff = (uint32_t)(row * 144 + seg * 16);
            cp_async16(buf + doff,
                       Ap + (size_t)(m0 + row) * HID + head * HDIM + k0 + seg * 8);
            cp_async16(buf + (uint32_t)(128 * 144) + doff,
                       Bp + ((size_t)head * 384 + n0 + row) * HDIM + k0 + seg * 8);
        }
    };

    auto load_frags = [&](uint32_t Ab, uint32_t Bb, int kk,
                          uint32_t af[2][4], uint32_t bf[8][2]) {
        #pragma unroll
        for (int slab = 0; slab < 2; slab++) {
            const int row = warp_m + slab * 16 + (lane & 15);
            const int col = kk + ((lane >> 4) << 3);
            ldm_x4(af[slab], Ab + (uint32_t)(row * SST + col) * 2);
        }
        const int g = lane >> 3;
        #pragma unroll
        for (int nb = 0; nb < 4; nb++) {
            const int nrow = warp_n + nb * 16 + ((g >> 1) << 3) + (lane & 7);
            const int col = kk + ((g & 1) << 3);
            uint32_t rr[4];
            ldm_x4(rr, Bb + (uint32_t)(nrow * SST + col) * 2);
            bf[nb * 2 + 0][0] = rr[0]; bf[nb * 2 + 0][1] = rr[1];
            bf[nb * 2 + 1][0] = rr[2]; bf[nb * 2 + 1][1] = rr[3];
        }
    };

    load_stage(0); cp_commit();
    load_stage(1); cp_commit();

    uint32_t af[2][2][4];
    uint32_t bf[2][8][2];

    for (int s = 0; s < Q_NSTAGES; ++s) {
        asm volatile("cp.async.wait_group 1;");
        __syncthreads();
        if (s + 2 < Q_NSTAGES) load_stage(s + 2);
        cp_commit();

        const uint32_t Ab = sbase + (uint32_t)(s % 3) * Q_STAGE;
        const uint32_t Bb = Ab + (uint32_t)(128 * 144);

        load_frags(Ab, Bb, 0, af[0], bf[0]);
        #pragma unroll
        for (int ki = 0; ki < 4; ki++) {
            const int cur = ki & 1;
            if (ki < 3)
                load_frags(Ab, Bb, (ki + 1) * 16, af[cur ^ 1], bf[cur ^ 1]);
            #pragma unroll
            for (int slab = 0; slab < 2; slab++)
                #pragma unroll
                for (int j = 0; j < 8; j++)
                    mma16816(c[slab][j], af[cur][slab], bf[cur][j]);
        }
    }

    const float kscale = 0.08838834764831845f;   // 1/sqrt(128)

    #pragma unroll
    for (int slab = 0; slab < 2; slab++) {
        const int mrow = m0 + warp_m + slab * 16 + (lane >> 2);
        #pragma unroll
        for (int j = 0; j < 8; j++) {
            const int ncol = n0 + warp_n + j * 8 + ((lane & 3) << 1);  // 0..383
            const int cls = ncol >> 7;          // 0:q 1:k 2:v
            float* outp = (cls == 0) ? g_q : ((cls == 1) ? g_k : g_v);
            const int colb = ncol & 127;
            const float b0 = bq[head * 384 + ncol];
            const float b1 = bq[head * 384 + ncol + 1];
            float t0 = c[slab][j][0] + b0, t1 = c[slab][j][1] + b1;
            float t2 = c[slab][j][2] + b0, t3 = c[slab][j][3] + b1;
            if (cls == 1) { t0 *= kscale; t1 *= kscale; t2 *= kscale; t3 *= kscale; }
            *(float2*)(outp + (size_t)mrow * HID + head * HDIM + colb) =
                make_float2(t0, t1);
            *(float2*)(outp + (size_t)(mrow + 8) * HID + head * HDIM + colb) =
                make_float2(t2, t3);
        }
    }
}

// ---------------------------------------------------------------------------
// Fused state update (memory-roofline bound on C traffic)
// ---------------------------------------------------------------------------
__global__ __launch_bounds__(128) void state_kernel(
    const float* __restrict__ Cin, const float* __restrict__ nin,
    float* __restrict__ out_h, float* __restrict__ out_C,
    float* __restrict__ out_n)
{
    __shared__ float q_s[128], k_s[128];
    __shared__ float f_s[128], a_s[128], o_s[128];
    __shared__ float red[4];
    __shared__ float s_inv;

    const int t = threadIdx.x;
    const int w = t >> 5;
    const int lane = t & 31;
    const int vo = blockIdx.x * HDIM;

    float iv = g_i[vo + t], fv = g_f[vo + t], ov = g_o[vo + t];
    float qv = g_q[vo + t], kv = g_k[vo + t], vv = g_v[vo + t];
    float nv = nin[vo + t];

    float nn = fv * nv + iv * kv;
    out_n[vo + t] = nn;

    q_s[t] = qv; k_s[t] = kv;
    f_s[t] = fv; a_s[t] = iv * vv; o_s[t] = ov;

    float p = nn * qv;
    #pragma unroll
    for (int off = 16; off; off >>= 1) p += __shfl_xor_sync(0xffffffffu, p, off);
    if (lane == 0) red[w] = p;
    __syncthreads();
    if (t == 0) {
        float dot = red[0] + red[1] + red[2] + red[3];
        s_inv = 1.0f / fmaxf(fabsf(dot), 1.0f);
    }
    __syncthreads();
    const float inv = s_inv;

    const float4 q4 = ((const float4*)q_s)[lane];
    const float4 k4 = ((const float4*)k_s)[lane];
    const float4* C4 = (const float4*)(Cin + (size_t)blockIdx.x * HDIM * HDIM);
    float4* O4 = (float4*)(out_C + (size_t)blockIdx.x * HDIM * HDIM);

    #pragma unroll 4
    for (int r = 0; r < 32; r++) {
        const int d = (w << 5) + r;
        float4 cc = C4[d * 32 + lane];
        float part = cc.x * q4.x + cc.y * q4.y + cc.z * q4.z + cc.w * q4.w;
        const float fd = f_s[d], ad = a_s[d];
        float4 cn;
        cn.x = fd * cc.x + ad * k4.x;
        cn.y = fd * cc.y + ad * k4.y;
        cn.z = fd * cc.z + ad * k4.z;
        cn.w = fd * cc.w + ad * k4.w;
        O4[d * 32 + lane] = cn;
        #pragma unroll
        for (int off = 16; off; off >>= 1)
            part += __shfl_xor_sync(0xffffffffu, part, off);
        if (lane == 0) out_h[vo + d] = o_s[d] * part * inv;
    }
}

// ---------------------------------------------------------------------------
// Launch
// ---------------------------------------------------------------------------
extern "C" void kernel_launch(void* const* d_in, const int* in_sizes, int n_in,
                              void* d_out, int out_size)
{
    const float* x     = (const float*)d_in[0];
    const float* C     = (const float*)d_in[2];
    const float* n     = (const float*)d_in[3];
    const float* W_i   = (const float*)d_in[4];
    const float* b_i   = (const float*)d_in[5];
    const float* W_qkv = (const float*)d_in[6];
    const float* b_qkv = (const float*)d_in[7];

    float* out   = (float*)d_out;
    float* out_h = out;
    float* out_C = out + (size_t)BATCH * HID;
    float* out_n = out_C + (size_t)BATCH * NHEAD * HDIM * HDIM;

    cudaFuncSetAttribute(gates_mma_kernel,
                         cudaFuncAttributeMaxDynamicSharedMemorySize, G_DSMEM);
    cudaFuncSetAttribute(qkv_mma_kernel,
                         cudaFuncAttributeMaxDynamicSharedMemorySize, Q_DSMEM);

    split_x_kernel<<<(BATCH * HID) / 256, 256>>>(x);
    splitT_w_kernel<<<dim3(N3 / 32, HID / 32), 256>>>(W_i);
    splitT_wq_kernel<<<dim3(384 / 32, HDIM / 32, NHEAD), 256>>>(W_qkv);
    gates_mma_kernel<<<dim3(N3 / 96, BATCH / 64), 256, G_DSMEM>>>(b_i);
    qkv_mma_kernel<<<dim3(384 / 128, BATCH / 128, NHEAD), 256, Q_DSMEM>>>(b_qkv);
    state_kernel<<<BATCH * NHEAD, 128>>>(C, n, out_h, out_C, out_n);
}

// round 9
// speedup vs baseline: 1.0588x; 1.0588x over previous
#include <cuda_runtime.h>
#include <cuda_bf16.h>
#include <cstdint>
#include <math.h>

#define BATCH 256
#define NHEAD 16
#define HDIM  128
#define HID   2048        // NHEAD * HDIM
#define N3    6144        // 3 * HID

// Scratch: activated gates and projections, [B, HID] each
__device__ __align__(16) float g_i[BATCH * HID];
__device__ __align__(16) float g_f[BATCH * HID];
__device__ __align__(16) float g_o[BATCH * HID];
__device__ __align__(16) float g_q[BATCH * HID];
__device__ __align__(16) float g_k[BATCH * HID];
__device__ __align__(16) float g_v[BATCH * HID];

// Split-precision scratch (bf16 hi/lo)
__device__ __align__(16) __nv_bfloat16 s_xh[BATCH * HID];
__device__ __align__(16) __nv_bfloat16 s_xl[BATCH * HID];
__device__ __align__(16) __nv_bfloat16 s_wh[(size_t)N3 * HID];   // W_i^T [6144,2048]
__device__ __align__(16) __nv_bfloat16 s_wl[(size_t)N3 * HID];
__device__ __align__(16) __nv_bfloat16 s_wqh[NHEAD * 384 * HDIM]; // W_qkv^T [h][384][128]
__device__ __align__(16) __nv_bfloat16 s_wql[NHEAD * 384 * HDIM];

// ---------------------------------------------------------------------------
// Split x -> bf16 hi/lo
// ---------------------------------------------------------------------------
__global__ __launch_bounds__(256) void split_x_kernel(const float* __restrict__ x)
{
    int idx = blockIdx.x * 256 + threadIdx.x;
    float v = x[idx];
    __nv_bfloat16 hi = __float2bfloat16(v);
    float lo = v - __bfloat162float(hi);
    s_xh[idx] = hi;
    s_xl[idx] = __float2bfloat16(lo);
}

// ---------------------------------------------------------------------------
// Split + transpose W_i [2048,6144] -> Wt hi/lo [6144,2048]
// ---------------------------------------------------------------------------
__global__ __launch_bounds__(256) void splitT_w_kernel(const float* __restrict__ W)
{
    __shared__ float tile[32][33];
    const int n0 = blockIdx.x * 32;
    const int k0 = blockIdx.y * 32;
    const int tx = threadIdx.x & 31;
    const int ty = threadIdx.x >> 5;   // 0..7

    #pragma unroll
    for (int j = 0; j < 4; j++)
        tile[ty + j * 8][tx] = W[(size_t)(k0 + ty + j * 8) * N3 + n0 + tx];
    __syncthreads();

    #pragma unroll
    for (int j = 0; j < 4; j++) {
        float v = tile[tx][ty + j * 8];
        __nv_bfloat16 hi = __float2bfloat16(v);
        float lo = v - __bfloat162float(hi);
        size_t o = (size_t)(n0 + ty + j * 8) * HID + k0 + tx;
        s_wh[o] = hi;
        s_wl[o] = __float2bfloat16(lo);
    }
}

// ---------------------------------------------------------------------------
// Split + transpose W_qkv [h][128][384] -> [h][384][128] hi/lo
// ---------------------------------------------------------------------------
__global__ __launch_bounds__(256) void splitT_wq_kernel(const float* __restrict__ Wq)
{
    __shared__ float tile[32][33];
    const int n0 = blockIdx.x * 32;     // 0..352
    const int k0 = blockIdx.y * 32;     // 0..96
    const int h  = blockIdx.z;
    const int tx = threadIdx.x & 31;
    const int ty = threadIdx.x >> 5;

    #pragma unroll
    for (int j = 0; j < 4; j++)
        tile[ty + j * 8][tx] = Wq[((size_t)h * HDIM + k0 + ty + j * 8) * 384 + n0 + tx];
    __syncthreads();

    #pragma unroll
    for (int j = 0; j < 4; j++) {
        float v = tile[tx][ty + j * 8];
        __nv_bfloat16 hi = __float2bfloat16(v);
        float lo = v - __bfloat162float(hi);
        size_t o = ((size_t)h * 384 + n0 + ty + j * 8) * HDIM + k0 + tx;
        s_wqh[o] = hi;
        s_wql[o] = __float2bfloat16(lo);
    }
}

// ---------------------------------------------------------------------------
// PTX helpers (sm_80-compatible: cp.async + ldmatrix + mma.sync)
// ---------------------------------------------------------------------------
__device__ __forceinline__ void cp_async16(uint32_t dst, const void* src) {
    asm volatile("cp.async.cg.shared.global [%0], [%1], 16;"
                 :: "r"(dst), "l"(src));
}
__device__ __forceinline__ void cp_commit() {
    asm volatile("cp.async.commit_group;");
}

__device__ __forceinline__ void ldm_x4(uint32_t* r, uint32_t addr) {
    asm volatile("ldmatrix.sync.aligned.m8n8.x4.shared.b16 {%0,%1,%2,%3}, [%4];"
                 : "=r"(r[0]), "=r"(r[1]), "=r"(r[2]), "=r"(r[3]) : "r"(addr));
}

__device__ __forceinline__ void mma16816(float* c, const uint32_t* a, const uint32_t* b) {
    asm volatile(
        "mma.sync.aligned.m16n8k16.row.col.f32.bf16.bf16.f32 "
        "{%0,%1,%2,%3}, {%4,%5,%6,%7}, {%8,%9}, {%0,%1,%2,%3};"
        : "+f"(c[0]), "+f"(c[1]), "+f"(c[2]), "+f"(c[3])
        : "r"(a[0]), "r"(a[1]), "r"(a[2]), "r"(a[3]), "r"(b[0]), "r"(b[1]));
}

#define SST 72                    // bf16 elems per smem row (144B = 9*16B)

// ===========================================================================
// Gates GEMM: D = Xh@Wh^T + Xl@Wh^T + Xh@Wl^T  (bf16x3 split precision)
// CTA tile 128x96, 256 threads, 8 warps 4Mx2N, warp tile 32x48.
// Grid 64x2 = 128 CTAs. BK=64, 5-stage cp.async ring (prefetch depth 4)
// to ride out DRAM latency on the streaming W tiles.
// ===========================================================================
#define GA_STAGE (128 * SST * 2)      // 18432
#define GB_STAGE (96 * SST * 2)       // 13824
#define G_STAGE (GA_STAGE + GB_STAGE) // 32256
#define G_NSTAGES 96
#define G_NRING 5
#define G_DSMEM (G_NRING * G_STAGE)   // 161280

__global__ __launch_bounds__(256, 1) void gates_mma_kernel(const float* __restrict__ bias)
{
    extern __shared__ __nv_bfloat16 smem[];

    const int tid = threadIdx.x;
    const int lane = tid & 31;
    const int wid = tid >> 5;
    const int warp_m = (wid & 3) * 32;     // 0,32,64,96
    const int warp_n = (wid >> 2) * 48;    // 0,48
    const int n0 = blockIdx.x * 96;
    const int m0 = blockIdx.y * 128;

    const int r_s = tid >> 3;              // 0..31
    const int seg = tid & 7;

    const uint32_t sbase = (uint32_t)__cvta_generic_to_shared(smem);

    float c[2][6][4];
    #pragma unroll
    for (int i = 0; i < 2; i++)
        #pragma unroll
        for (int j = 0; j < 6; j++)
            #pragma unroll
            for (int q = 0; q < 4; q++) c[i][j][q] = 0.0f;

    auto load_stage = [&](int s) {
        const int term = s >> 5;
        const int k0 = (s & 31) << 6;
        const __nv_bfloat16* Ap = (term == 1) ? s_xl : s_xh;
        const __nv_bfloat16* Bp = (term == 2) ? s_wl : s_wh;
        const uint32_t buf = sbase + (uint32_t)(s % G_NRING) * G_STAGE;
        #pragma unroll
        for (int h = 0; h < 4; h++) {
            const int row = r_s + h * 32;
            cp_async16(buf + (uint32_t)(row * 144 + seg * 16),
                       Ap + (size_t)(m0 + row) * HID + k0 + seg * 8);
        }
        #pragma unroll
        for (int h = 0; h < 3; h++) {
            const int row = r_s + h * 32;
            cp_async16(buf + GA_STAGE + (uint32_t)(row * 144 + seg * 16),
                       Bp + (size_t)(n0 + row) * HID + k0 + seg * 8);
        }
    };

    auto load_frags = [&](uint32_t Ab, uint32_t Bb, int kk,
                          uint32_t af[2][4], uint32_t bf[6][2]) {
        #pragma unroll
        for (int slab = 0; slab < 2; slab++) {
            const int row = warp_m + slab * 16 + (lane & 15);
            const int col = kk + ((lane >> 4) << 3);
            ldm_x4(af[slab], Ab + (uint32_t)(row * SST + col) * 2);
        }
        const int g = lane >> 3;
        #pragma unroll
        for (int nb = 0; nb < 3; nb++) {
            const int nrow = warp_n + nb * 16 + ((g >> 1) << 3) + (lane & 7);
            const int col = kk + ((g & 1) << 3);
            uint32_t rr[4];
            ldm_x4(rr, Bb + (uint32_t)(nrow * SST + col) * 2);
            bf[nb * 2 + 0][0] = rr[0]; bf[nb * 2 + 0][1] = rr[1];
            bf[nb * 2 + 1][0] = rr[2]; bf[nb * 2 + 1][1] = rr[3];
        }
    };

    load_stage(0); cp_commit();
    load_stage(1); cp_commit();
    load_stage(2); cp_commit();
    load_stage(3); cp_commit();

    uint32_t af[2][2][4];
    uint32_t bf[2][6][2];

    for (int s = 0; s < G_NSTAGES; ++s) {
        asm volatile("cp.async.wait_group 3;");
        __syncthreads();
        if (s + 4 < G_NSTAGES) load_stage(s + 4);
        cp_commit();

        const uint32_t Ab = sbase + (uint32_t)(s % G_NRING) * G_STAGE;
        const uint32_t Bb = Ab + GA_STAGE;

        load_frags(Ab, Bb, 0, af[0], bf[0]);
        #pragma unroll
        for (int ki = 0; ki < 4; ki++) {
            const int cur = ki & 1;
            if (ki < 3)
                load_frags(Ab, Bb, (ki + 1) * 16, af[cur ^ 1], bf[cur ^ 1]);
            #pragma unroll
            for (int slab = 0; slab < 2; slab++)
                #pragma unroll
                for (int j = 0; j < 6; j++)
                    mma16816(c[slab][j], af[cur][slab], bf[cur][j]);
        }
    }

    // Epilogue: per-column gate class (pair never straddles a class boundary)
    #pragma unroll
    for (int slab = 0; slab < 2; slab++) {
        const int mrow = m0 + warp_m + slab * 16 + (lane >> 2);
        #pragma unroll
        for (int j = 0; j < 6; j++) {
            const int col = n0 + warp_n + j * 8 + ((lane & 3) << 1);
            const int cls = col >> 11;          // 0:i 1:f 2:o
            float* outp = (cls == 0) ? g_i : ((cls == 1) ? g_f : g_o);
            const int cb = col & 2047;
            const float b0 = bias[col], b1 = bias[col + 1];
            float t0 = c[slab][j][0] + b0, t1 = c[slab][j][1] + b1;
            float t2 = c[slab][j][2] + b0, t3 = c[slab][j][3] + b1;
            float2 v0, v1;
            if (cls == 2) {
                v0.x = 1.0f / (1.0f + expf(-t0));
                v0.y = 1.0f / (1.0f + expf(-t1));
                v1.x = 1.0f / (1.0f + expf(-t2));
                v1.y = 1.0f / (1.0f + expf(-t3));
            } else {
                v0.x = expf(t0); v0.y = expf(t1);
                v1.x = expf(t2); v1.y = expf(t3);
            }
            *(float2*)(outp + (size_t)mrow * HID + cb) = v0;
            *(float2*)(outp + (size_t)(mrow + 8) * HID + cb) = v1;
        }
    }
}

// ===========================================================================
// QKV GEMM (per-head, bf16x3): M=256, N=384, K=128 per head.
// CTA tile 128x128, grid (3, 2, 16) = 96 CTAs, 6 stages of BK=64.
// ===========================================================================
#define Q_STAGE (2 * 128 * SST * 2)   // 36864 (A + B, both 128 rows)
#define Q_NSTAGES 6
#define Q_DSMEM (3 * Q_STAGE)         // 110592

__global__ __launch_bounds__(256, 1) void qkv_mma_kernel(const float* __restrict__ bq)
{
    extern __shared__ __nv_bfloat16 smem[];

    const int tid = threadIdx.x;
    const int lane = tid & 31;
    const int wid = tid >> 5;
    const int warp_m = (wid & 3) * 32;
    const int warp_n = (wid >> 2) * 64;
    const int n0 = blockIdx.x * 128;       // 0,128,256 (of 384)
    const int m0 = blockIdx.y * 128;
    const int head = blockIdx.z;

    const int r_s = tid >> 3;
    const int seg = tid & 7;

    const uint32_t sbase = (uint32_t)__cvta_generic_to_shared(smem);

    float c[2][8][4];
    #pragma unroll
    for (int i = 0; i < 2; i++)
        #pragma unroll
        for (int j = 0; j < 8; j++)
            #pragma unroll
            for (int q = 0; q < 4; q++) c[i][j][q] = 0.0f;

    auto load_stage = [&](int s) {
        const int term = s >> 1;           // 0,1,2
        const int k0 = (s & 1) << 6;
        const __nv_bfloat16* Ap = (term == 1) ? s_xl : s_xh;
        const __nv_bfloat16* Bp = (term == 2) ? s_wql : s_wqh;
        const uint32_t buf = sbase + (uint32_t)(s % 3) * Q_STAGE;
        #pragma unroll
        for (int h = 0; h < 4; h++) {
            const int row = r_s + h * 32;
            const uint32_t doff = (uint32_t)(row * 144 + seg * 16);
            cp_async16(buf + doff,
                       Ap + (size_t)(m0 + row) * HID + head * HDIM + k0 + seg * 8);
            cp_async16(buf + (uint32_t)(128 * 144) + doff,
                       Bp + ((size_t)head * 384 + n0 + row) * HDIM + k0 + seg * 8);
        }
    };

    auto load_frags = [&](uint32_t Ab, uint32_t Bb, int kk,
                          uint32_t af[2][4], uint32_t bf[8][2]) {
        #pragma unroll
        for (int slab = 0; slab < 2; slab++) {
            const int row = warp_m + slab * 16 + (lane & 15);
            const int col = kk + ((lane >> 4) << 3);
            ldm_x4(af[slab], Ab + (uint32_t)(row * SST + col) * 2);
        }
        const int g = lane >> 3;
        #pragma unroll
        for (int nb = 0; nb < 4; nb++) {
            const int nrow = warp_n + nb * 16 + ((g >> 1) << 3) + (lane & 7);
            const int col = kk + ((g & 1) << 3);
            uint32_t rr[4];
            ldm_x4(rr, Bb + (uint32_t)(nrow * SST + col) * 2);
            bf[nb * 2 + 0][0] = rr[0]; bf[nb * 2 + 0][1] = rr[1];
            bf[nb * 2 + 1][0] = rr[2]; bf[nb * 2 + 1][1] = rr[3];
        }
    };

    load_stage(0); cp_commit();
    load_stage(1); cp_commit();

    uint32_t af[2][2][4];
    uint32_t bf[2][8][2];

    for (int s = 0; s < Q_NSTAGES; ++s) {
        asm volatile("cp.async.wait_group 1;");
        __syncthreads();
        if (s + 2 < Q_NSTAGES) load_stage(s + 2);
        cp_commit();

        const uint32_t Ab = sbase + (uint32_t)(s % 3) * Q_STAGE;
        const uint32_t Bb = Ab + (uint32_t)(128 * 144);

        load_frags(Ab, Bb, 0, af[0], bf[0]);
        #pragma unroll
        for (int ki = 0; ki < 4; ki++) {
            const int cur = ki & 1;
            if (ki < 3)
                load_frags(Ab, Bb, (ki + 1) * 16, af[cur ^ 1], bf[cur ^ 1]);
            #pragma unroll
            for (int slab = 0; slab < 2; slab++)
                #pragma unroll
                for (int j = 0; j < 8; j++)
                    mma16816(c[slab][j], af[cur][slab], bf[cur][j]);
        }
    }

    const float kscale = 0.08838834764831845f;   // 1/sqrt(128)

    #pragma unroll
    for (int slab = 0; slab < 2; slab++) {
        const int mrow = m0 + warp_m + slab * 16 + (lane >> 2);
        #pragma unroll
        for (int j = 0; j < 8; j++) {
            const int ncol = n0 + warp_n + j * 8 + ((lane & 3) << 1);  // 0..383
            const int cls = ncol >> 7;          // 0:q 1:k 2:v
            float* outp = (cls == 0) ? g_q : ((cls == 1) ? g_k : g_v);
            const int colb = ncol & 127;
            const float b0 = bq[head * 384 + ncol];
            const float b1 = bq[head * 384 + ncol + 1];
            float t0 = c[slab][j][0] + b0, t1 = c[slab][j][1] + b1;
            float t2 = c[slab][j][2] + b0, t3 = c[slab][j][3] + b1;
            if (cls == 1) { t0 *= kscale; t1 *= kscale; t2 *= kscale; t3 *= kscale; }
            *(float2*)(outp + (size_t)mrow * HID + head * HDIM + colb) =
                make_float2(t0, t1);
            *(float2*)(outp + (size_t)(mrow + 8) * HID + head * HDIM + colb) =
                make_float2(t2, t3);
        }
    }
}

// ---------------------------------------------------------------------------
// Fused state update (memory-roofline bound on C traffic)
// ---------------------------------------------------------------------------
__global__ __launch_bounds__(128) void state_kernel(
    const float* __restrict__ Cin, const float* __restrict__ nin,
    float* __restrict__ out_h, float* __restrict__ out_C,
    float* __restrict__ out_n)
{
    __shared__ float q_s[128], k_s[128];
    __shared__ float f_s[128], a_s[128], o_s[128];
    __shared__ float red[4];
    __shared__ float s_inv;

    const int t = threadIdx.x;
    const int w = t >> 5;
    const int lane = t & 31;
    const int vo = blockIdx.x * HDIM;

    float iv = g_i[vo + t], fv = g_f[vo + t], ov = g_o[vo + t];
    float qv = g_q[vo + t], kv = g_k[vo + t], vv = g_v[vo + t];
    float nv = nin[vo + t];

    float nn = fv * nv + iv * kv;
    out_n[vo + t] = nn;

    q_s[t] = qv; k_s[t] = kv;
    f_s[t] = fv; a_s[t] = iv * vv; o_s[t] = ov;

    float p = nn * qv;
    #pragma unroll
    for (int off = 16; off; off >>= 1) p += __shfl_xor_sync(0xffffffffu, p, off);
    if (lane == 0) red[w] = p;
    __syncthreads();
    if (t == 0) {
        float dot = red[0] + red[1] + red[2] + red[3];
        s_inv = 1.0f / fmaxf(fabsf(dot), 1.0f);
    }
    __syncthreads();
    const float inv = s_inv;

    const float4 q4 = ((const float4*)q_s)[lane];
    const float4 k4 = ((const float4*)k_s)[lane];
    const float4* C4 = (const float4*)(Cin + (size_t)blockIdx.x * HDIM * HDIM);
    float4* O4 = (float4*)(out_C + (size_t)blockIdx.x * HDIM * HDIM);

    #pragma unroll 4
    for (int r = 0; r < 32; r++) {
        const int d = (w << 5) + r;
        float4 cc = C4[d * 32 + lane];
        float part = cc.x * q4.x + cc.y * q4.y + cc.z * q4.z + cc.w * q4.w;
        const float fd = f_s[d], ad = a_s[d];
        float4 cn;
        cn.x = fd * cc.x + ad * k4.x;
        cn.y = fd * cc.y + ad * k4.y;
        cn.z = fd * cc.z + ad * k4.z;
        cn.w = fd * cc.w + ad * k4.w;
        O4[d * 32 + lane] = cn;
        #pragma unroll
        for (int off = 16; off; off >>= 1)
            part += __shfl_xor_sync(0xffffffffu, part, off);
        if (lane == 0) out_h[vo + d] = o_s[d] * part * inv;
    }
}

// ---------------------------------------------------------------------------
// Launch
// ---------------------------------------------------------------------------
extern "C" void kernel_launch(void* const* d_in, const int* in_sizes, int n_in,
                              void* d_out, int out_size)
{
    const float* x     = (const float*)d_in[0];
    const float* C     = (const float*)d_in[2];
    const float* n     = (const float*)d_in[3];
    const float* W_i   = (const float*)d_in[4];
    const float* b_i   = (const float*)d_in[5];
    const float* W_qkv = (const float*)d_in[6];
    const float* b_qkv = (const float*)d_in[7];

    float* out   = (float*)d_out;
    float* out_h = out;
    float* out_C = out + (size_t)BATCH * HID;
    float* out_n = out_C + (size_t)BATCH * NHEAD * HDIM * HDIM;

    cudaFuncSetAttribute(gates_mma_kernel,
                         cudaFuncAttributeMaxDynamicSharedMemorySize, G_DSMEM);
    cudaFuncSetAttribute(qkv_mma_kernel,
                         cudaFuncAttributeMaxDynamicSharedMemorySize, Q_DSMEM);

    split_x_kernel<<<(BATCH * HID) / 256, 256>>>(x);
    splitT_w_kernel<<<dim3(N3 / 32, HID / 32), 256>>>(W_i);
    splitT_wq_kernel<<<dim3(384 / 32, HDIM / 32, NHEAD), 256>>>(W_qkv);
    gates_mma_kernel<<<dim3(N3 / 96, BATCH / 128), 256, G_DSMEM>>>(b_i);
    qkv_mma_kernel<<<dim3(384 / 128, BATCH / 128, NHEAD), 256, Q_DSMEM>>>(b_qkv);
    state_kernel<<<BATCH * NHEAD, 128>>>(C, n, out_h, out_C, out_n);
}

// round 10
// speedup vs baseline: 1.1132x; 1.0514x over previous
#include <cuda_runtime.h>
#include <cuda_bf16.h>
#include <cstdint>
#include <math.h>

#define BATCH 256
#define NHEAD 16
#define HDIM  128
#define HID   2048        // NHEAD * HDIM
#define N3    6144        // 3 * HID

// Scratch: activated gates and projections, [B, HID] each
__device__ __align__(16) float g_i[BATCH * HID];
__device__ __align__(16) float g_f[BATCH * HID];
__device__ __align__(16) float g_o[BATCH * HID];
__device__ __align__(16) float g_q[BATCH * HID];
__device__ __align__(16) float g_k[BATCH * HID];
__device__ __align__(16) float g_v[BATCH * HID];

// Split-K partial accumulators for gates GEMM  [B, N3] each
__device__ __align__(16) float g_pa[(size_t)BATCH * N3];
__device__ __align__(16) float g_pb[(size_t)BATCH * N3];

// Split-precision scratch (bf16 hi/lo)
__device__ __align__(16) __nv_bfloat16 s_xh[BATCH * HID];
__device__ __align__(16) __nv_bfloat16 s_xl[BATCH * HID];
__device__ __align__(16) __nv_bfloat16 s_wh[(size_t)N3 * HID];   // W_i^T [6144,2048]
__device__ __align__(16) __nv_bfloat16 s_wl[(size_t)N3 * HID];
__device__ __align__(16) __nv_bfloat16 s_wqh[NHEAD * 384 * HDIM]; // W_qkv^T [h][384][128]
__device__ __align__(16) __nv_bfloat16 s_wql[NHEAD * 384 * HDIM];

// ---------------------------------------------------------------------------
// Split x -> bf16 hi/lo
// ---------------------------------------------------------------------------
__global__ __launch_bounds__(256) void split_x_kernel(const float* __restrict__ x)
{
    int idx = blockIdx.x * 256 + threadIdx.x;
    float v = x[idx];
    __nv_bfloat16 hi = __float2bfloat16(v);
    float lo = v - __bfloat162float(hi);
    s_xh[idx] = hi;
    s_xl[idx] = __float2bfloat16(lo);
}

// ---------------------------------------------------------------------------
// Split + transpose W_i [2048,6144] -> Wt hi/lo [6144,2048]
// ---------------------------------------------------------------------------
__global__ __launch_bounds__(256) void splitT_w_kernel(const float* __restrict__ W)
{
    __shared__ float tile[32][33];
    const int n0 = blockIdx.x * 32;
    const int k0 = blockIdx.y * 32;
    const int tx = threadIdx.x & 31;
    const int ty = threadIdx.x >> 5;   // 0..7

    #pragma unroll
    for (int j = 0; j < 4; j++)
        tile[ty + j * 8][tx] = W[(size_t)(k0 + ty + j * 8) * N3 + n0 + tx];
    __syncthreads();

    #pragma unroll
    for (int j = 0; j < 4; j++) {
        float v = tile[tx][ty + j * 8];
        __nv_bfloat16 hi = __float2bfloat16(v);
        float lo = v - __bfloat162float(hi);
        size_t o = (size_t)(n0 + ty + j * 8) * HID + k0 + tx;
        s_wh[o] = hi;
        s_wl[o] = __float2bfloat16(lo);
    }
}

// ---------------------------------------------------------------------------
// Split + transpose W_qkv [h][128][384] -> [h][384][128] hi/lo
// ---------------------------------------------------------------------------
__global__ __launch_bounds__(256) void splitT_wq_kernel(const float* __restrict__ Wq)
{
    __shared__ float tile[32][33];
    const int n0 = blockIdx.x * 32;     // 0..352
    const int k0 = blockIdx.y * 32;     // 0..96
    const int h  = blockIdx.z;
    const int tx = threadIdx.x & 31;
    const int ty = threadIdx.x >> 5;

    #pragma unroll
    for (int j = 0; j < 4; j++)
        tile[ty + j * 8][tx] = Wq[((size_t)h * HDIM + k0 + ty + j * 8) * 384 + n0 + tx];
    __syncthreads();

    #pragma unroll
    for (int j = 0; j < 4; j++) {
        float v = tile[tx][ty + j * 8];
        __nv_bfloat16 hi = __float2bfloat16(v);
        float lo = v - __bfloat162float(hi);
        size_t o = ((size_t)h * 384 + n0 + ty + j * 8) * HDIM + k0 + tx;
        s_wqh[o] = hi;
        s_wql[o] = __float2bfloat16(lo);
    }
}

// ---------------------------------------------------------------------------
// PTX helpers (sm_80-compatible: cp.async + ldmatrix + mma.sync)
// ---------------------------------------------------------------------------
__device__ __forceinline__ void cp_async16(uint32_t dst, const void* src) {
    asm volatile("cp.async.cg.shared.global [%0], [%1], 16;"
                 :: "r"(dst), "l"(src));
}
__device__ __forceinline__ void cp_commit() {
    asm volatile("cp.async.commit_group;");
}

__device__ __forceinline__ void ldm_x4(uint32_t* r, uint32_t addr) {
    asm volatile("ldmatrix.sync.aligned.m8n8.x4.shared.b16 {%0,%1,%2,%3}, [%4];"
                 : "=r"(r[0]), "=r"(r[1]), "=r"(r[2]), "=r"(r[3]) : "r"(addr));
}

__device__ __forceinline__ void mma16816(float* c, const uint32_t* a, const uint32_t* b) {
    asm volatile(
        "mma.sync.aligned.m16n8k16.row.col.f32.bf16.bf16.f32 "
        "{%0,%1,%2,%3}, {%4,%5,%6,%7}, {%8,%9}, {%0,%1,%2,%3};"
        : "+f"(c[0]), "+f"(c[1]), "+f"(c[2]), "+f"(c[3])
        : "r"(a[0]), "r"(a[1]), "r"(a[2]), "r"(a[3]), "r"(b[0]), "r"(b[1]));
}

#define SST 72                    // bf16 elems per smem row (144B = 9*16B)

// ===========================================================================
// Gates GEMM, split-K=2: D = Xh@Wh^T + Xl@Wh^T + Xh@Wl^T (bf16x3)
// CTA tile 128x96, 256 threads, 8 warps 4Mx2N, warp tile 32x48.
// Grid (64, 2, 2): z splits the 96 K-stages in half -> 256 CTAs,
// 2 CTAs/SM co-resident (3-stage ring, 96.8KB smem each).
// Raw fp32 partials to g_pa / g_pb; activation in gates_epi_kernel.
// ===========================================================================
#define GA_STAGE (128 * SST * 2)      // 18432
#define GB_STAGE (96 * SST * 2)       // 13824
#define G_STAGE (GA_STAGE + GB_STAGE) // 32256
#define G_NSTAGES 96
#define G_HALF 48
#define G_DSMEM (3 * G_STAGE)         // 96768

__global__ __launch_bounds__(256, 2) void gates_mma_kernel(void)
{
    extern __shared__ __nv_bfloat16 smem[];

    const int tid = threadIdx.x;
    const int lane = tid & 31;
    const int wid = tid >> 5;
    const int warp_m = (wid & 3) * 32;     // 0,32,64,96
    const int warp_n = (wid >> 2) * 48;    // 0,48
    const int n0 = blockIdx.x * 96;
    const int m0 = blockIdx.y * 128;
    const int sbase_k = blockIdx.z * G_HALF;   // 0 or 48

    const int r_s = tid >> 3;              // 0..31
    const int seg = tid & 7;

    const uint32_t sbase = (uint32_t)__cvta_generic_to_shared(smem);

    float c[2][6][4];
    #pragma unroll
    for (int i = 0; i < 2; i++)
        #pragma unroll
        for (int j = 0; j < 6; j++)
            #pragma unroll
            for (int q = 0; q < 4; q++) c[i][j][q] = 0.0f;

    auto load_stage = [&](int sl) {
        const int s = sbase_k + sl;        // global stage id
        const int term = s >> 5;
        const int k0 = (s & 31) << 6;
        const __nv_bfloat16* Ap = (term == 1) ? s_xl : s_xh;
        const __nv_bfloat16* Bp = (term == 2) ? s_wl : s_wh;
        const uint32_t buf = sbase + (uint32_t)(sl % 3) * G_STAGE;
        #pragma unroll
        for (int h = 0; h < 4; h++) {
            const int row = r_s + h * 32;
            cp_async16(buf + (uint32_t)(row * 144 + seg * 16),
                       Ap + (size_t)(m0 + row) * HID + k0 + seg * 8);
        }
        #pragma unroll
        for (int h = 0; h < 3; h++) {
            const int row = r_s + h * 32;
            cp_async16(buf + GA_STAGE + (uint32_t)(row * 144 + seg * 16),
                       Bp + (size_t)(n0 + row) * HID + k0 + seg * 8);
        }
    };

    auto load_frags = [&](uint32_t Ab, uint32_t Bb, int kk,
                          uint32_t af[2][4], uint32_t bf[6][2]) {
        #pragma unroll
        for (int slab = 0; slab < 2; slab++) {
            const int row = warp_m + slab * 16 + (lane & 15);
            const int col = kk + ((lane >> 4) << 3);
            ldm_x4(af[slab], Ab + (uint32_t)(row * SST + col) * 2);
        }
        const int g = lane >> 3;
        #pragma unroll
        for (int nb = 0; nb < 3; nb++) {
            const int nrow = warp_n + nb * 16 + ((g >> 1) << 3) + (lane & 7);
            const int col = kk + ((g & 1) << 3);
            uint32_t rr[4];
            ldm_x4(rr, Bb + (uint32_t)(nrow * SST + col) * 2);
            bf[nb * 2 + 0][0] = rr[0]; bf[nb * 2 + 0][1] = rr[1];
            bf[nb * 2 + 1][0] = rr[2]; bf[nb * 2 + 1][1] = rr[3];
        }
    };

    load_stage(0); cp_commit();
    load_stage(1); cp_commit();

    uint32_t af[2][2][4];
    uint32_t bf[2][6][2];

    for (int sl = 0; sl < G_HALF; ++sl) {
        asm volatile("cp.async.wait_group 1;");
        __syncthreads();
        if (sl + 2 < G_HALF) load_stage(sl + 2);
        cp_commit();

        const uint32_t Ab = sbase + (uint32_t)(sl % 3) * G_STAGE;
        const uint32_t Bb = Ab + GA_STAGE;

        load_frags(Ab, Bb, 0, af[0], bf[0]);
        #pragma unroll
        for (int ki = 0; ki < 4; ki++) {
            const int cur = ki & 1;
            if (ki < 3)
                load_frags(Ab, Bb, (ki + 1) * 16, af[cur ^ 1], bf[cur ^ 1]);
            #pragma unroll
            for (int slab = 0; slab < 2; slab++)
                #pragma unroll
                for (int j = 0; j < 6; j++)
                    mma16816(c[slab][j], af[cur][slab], bf[cur][j]);
        }
    }

    // Store raw fp32 partials
    float* pout = (blockIdx.z == 0) ? g_pa : g_pb;
    #pragma unroll
    for (int slab = 0; slab < 2; slab++) {
        const int mrow = m0 + warp_m + slab * 16 + (lane >> 2);
        #pragma unroll
        for (int j = 0; j < 6; j++) {
            const int col = n0 + warp_n + j * 8 + ((lane & 3) << 1);
            *(float2*)(pout + (size_t)mrow * N3 + col) =
                make_float2(c[slab][j][0], c[slab][j][1]);
            *(float2*)(pout + (size_t)(mrow + 8) * N3 + col) =
                make_float2(c[slab][j][2], c[slab][j][3]);
        }
    }
}

// ---------------------------------------------------------------------------
// Gates epilogue: act(pa + pb + bias) -> g_i / g_f / g_o
// ---------------------------------------------------------------------------
__global__ __launch_bounds__(256) void gates_epi_kernel(const float* __restrict__ bias)
{
    const int idx4 = blockIdx.x * 256 + threadIdx.x;   // float4 index
    const int m = idx4 / (N3 / 4);
    const int col = (idx4 % (N3 / 4)) * 4;

    float4 a = *(const float4*)(g_pa + (size_t)m * N3 + col);
    float4 b = *(const float4*)(g_pb + (size_t)m * N3 + col);
    float4 bi = *(const float4*)(bias + col);

    float t0 = a.x + b.x + bi.x;
    float t1 = a.y + b.y + bi.y;
    float t2 = a.z + b.z + bi.z;
    float t3 = a.w + b.w + bi.w;

    const int cls = col >> 11;          // 0:i 1:f 2:o (float4 never straddles)
    float* outp = (cls == 0) ? g_i : ((cls == 1) ? g_f : g_o);
    float4 v;
    if (cls == 2) {
        v.x = 1.0f / (1.0f + expf(-t0));
        v.y = 1.0f / (1.0f + expf(-t1));
        v.z = 1.0f / (1.0f + expf(-t2));
        v.w = 1.0f / (1.0f + expf(-t3));
    } else {
        v.x = expf(t0); v.y = expf(t1); v.z = expf(t2); v.w = expf(t3);
    }
    *(float4*)(outp + (size_t)m * HID + (col & 2047)) = v;
}

// ===========================================================================
// QKV GEMM (per-head, bf16x3): M=256, N=384, K=128 per head.
// CTA tile 128x128, grid (3, 2, 16) = 96 CTAs, 6 stages of BK=64.
// ===========================================================================
#define Q_STAGE (2 * 128 * SST * 2)   // 36864 (A + B, both 128 rows)
#define Q_NSTAGES 6
#define Q_DSMEM (3 * Q_STAGE)         // 110592

__global__ __launch_bounds__(256, 1) void qkv_mma_kernel(const float* __restrict__ bq)
{
    extern __shared__ __nv_bfloat16 smem[];

    const int tid = threadIdx.x;
    const int lane = tid & 31;
    const int wid = tid >> 5;
    const int warp_m = (wid & 3) * 32;
    const int warp_n = (wid >> 2) * 64;
    const int n0 = blockIdx.x * 128;       // 0,128,256 (of 384)
    const int m0 = blockIdx.y * 128;
    const int head = blockIdx.z;

    const int r_s = tid >> 3;
    const int seg = tid & 7;

    const uint32_t sbase = (uint32_t)__cvta_generic_to_shared(smem);

    float c[2][8][4];
    #pragma unroll
    for (int i = 0; i < 2; i++)
        #pragma unroll
        for (int j = 0; j < 8; j++)
            #pragma unroll
            for (int q = 0; q < 4; q++) c[i][j][q] = 0.0f;

    auto load_stage = [&](int s) {
        const int term = s >> 1;           // 0,1,2
        const int k0 = (s & 1) << 6;
        const __nv_bfloat16* Ap = (term == 1) ? s_xl : s_xh;
        const __nv_bfloat16* Bp = (term == 2) ? s_wql : s_wqh;
        const uint32_t buf = sbase + (uint32_t)(s % 3) * Q_STAGE;
        #pragma unroll
        for (int h = 0; h < 4; h++) {
            const int row = r_s + h * 32;
            const uint32_t doff = (uint32_t)(row * 144 + seg * 16);
            cp_async16(buf + doff,
                       Ap + (size_t)(m0 + row) * HID + head * HDIM + k0 + seg * 8);
            cp_async16(buf + (uint32_t)(128 * 144) + doff,
                       Bp + ((size_t)head * 384 + n0 + row) * HDIM + k0 + seg * 8);
        }
    };

    auto load_frags = [&](uint32_t Ab, uint32_t Bb, int kk,
                          uint32_t af[2][4], uint32_t bf[8][2]) {
        #pragma unroll
        for (int slab = 0; slab < 2; slab++) {
            const int row = warp_m + slab * 16 + (lane & 15);
            const int col = kk + ((lane >> 4) << 3);
            ldm_x4(af[slab], Ab + (uint32_t)(row * SST + col) * 2);
        }
        const int g = lane >> 3;
        #pragma unroll
        for (int nb = 0; nb < 4; nb++) {
            const int nrow = warp_n + nb * 16 + ((g >> 1) << 3) + (lane & 7);
            const int col = kk + ((g & 1) << 3);
            uint32_t rr[4];
            ldm_x4(rr, Bb + (uint32_t)(nrow * SST + col) * 2);
            bf[nb * 2 + 0][0] = rr[0]; bf[nb * 2 + 0][1] = rr[1];
            bf[nb * 2 + 1][0] = rr[2]; bf[nb * 2 + 1][1] = rr[3];
        }
    };

    load_stage(0); cp_commit();
    load_stage(1); cp_commit();

    uint32_t af[2][2][4];
    uint32_t bf[2][8][2];

    for (int s = 0; s < Q_NSTAGES; ++s) {
        asm volatile("cp.async.wait_group 1;");
        __syncthreads();
        if (s + 2 < Q_NSTAGES) load_stage(s + 2);
        cp_commit();

        const uint32_t Ab = sbase + (uint32_t)(s % 3) * Q_STAGE;
        const uint32_t Bb = Ab + (uint32_t)(128 * 144);

        load_frags(Ab, Bb, 0, af[0], bf[0]);
        #pragma unroll
        for (int ki = 0; ki < 4; ki++) {
            const int cur = ki & 1;
            if (ki < 3)
                load_frags(Ab, Bb, (ki + 1) * 16, af[cur ^ 1], bf[cur ^ 1]);
            #pragma unroll
            for (int slab = 0; slab < 2; slab++)
                #pragma unroll
                for (int j = 0; j < 8; j++)
                    mma16816(c[slab][j], af[cur][slab], bf[cur][j]);
        }
    }

    const float kscale = 0.08838834764831845f;   // 1/sqrt(128)

    #pragma unroll
    for (int slab = 0; slab < 2; slab++) {
        const int mrow = m0 + warp_m + slab * 16 + (lane >> 2);
        #pragma unroll
        for (int j = 0; j < 8; j++) {
            const int ncol = n0 + warp_n + j * 8 + ((lane & 3) << 1);  // 0..383
            const int cls = ncol >> 7;          // 0:q 1:k 2:v
            float* outp = (cls == 0) ? g_q : ((cls == 1) ? g_k : g_v);
            const int colb = ncol & 127;
            const float b0 = bq[head * 384 + ncol];
            const float b1 = bq[head * 384 + ncol + 1];
            float t0 = c[slab][j][0] + b0, t1 = c[slab][j][1] + b1;
            float t2 = c[slab][j][2] + b0, t3 = c[slab][j][3] + b1;
            if (cls == 1) { t0 *= kscale; t1 *= kscale; t2 *= kscale; t3 *= kscale; }
            *(float2*)(outp + (size_t)mrow * HID + head * HDIM + colb) =
                make_float2(t0, t1);
            *(float2*)(outp + (size_t)(mrow + 8) * HID + head * HDIM + colb) =
                make_float2(t2, t3);
        }
    }
}

// ---------------------------------------------------------------------------
// Fused state update (memory-roofline bound on C traffic)
// ---------------------------------------------------------------------------
__global__ __launch_bounds__(128) void state_kernel(
    const float* __restrict__ Cin, const float* __restrict__ nin,
    float* __restrict__ out_h, float* __restrict__ out_C,
    float* __restrict__ out_n)
{
    __shared__ float q_s[128], k_s[128];
    __shared__ float f_s[128], a_s[128], o_s[128];
    __shared__ float red[4];
    __shared__ float s_inv;

    const int t = threadIdx.x;
    const int w = t >> 5;
    const int lane = t & 31;
    const int vo = blockIdx.x * HDIM;

    float iv = g_i[vo + t], fv = g_f[vo + t], ov = g_o[vo + t];
    float qv = g_q[vo + t], kv = g_k[vo + t], vv = g_v[vo + t];
    float nv = nin[vo + t];

    float nn = fv * nv + iv * kv;
    out_n[vo + t] = nn;

    q_s[t] = qv; k_s[t] = kv;
    f_s[t] = fv; a_s[t] = iv * vv; o_s[t] = ov;

    float p = nn * qv;
    #pragma unroll
    for (int off = 16; off; off >>= 1) p += __shfl_xor_sync(0xffffffffu, p, off);
    if (lane == 0) red[w] = p;
    __syncthreads();
    if (t == 0) {
        float dot = red[0] + red[1] + red[2] + red[3];
        s_inv = 1.0f / fmaxf(fabsf(dot), 1.0f);
    }
    __syncthreads();
    const float inv = s_inv;

    const float4 q4 = ((const float4*)q_s)[lane];
    const float4 k4 = ((const float4*)k_s)[lane];
    const float4* C4 = (const float4*)(Cin + (size_t)blockIdx.x * HDIM * HDIM);
    float4* O4 = (float4*)(out_C + (size_t)blockIdx.x * HDIM * HDIM);

    #pragma unroll 4
    for (int r = 0; r < 32; r++) {
        const int d = (w << 5) + r;
        float4 cc = C4[d * 32 + lane];
        float part = cc.x * q4.x + cc.y * q4.y + cc.z * q4.z + cc.w * q4.w;
        const float fd = f_s[d], ad = a_s[d];
        float4 cn;
        cn.x = fd * cc.x + ad * k4.x;
        cn.y = fd * cc.y + ad * k4.y;
        cn.z = fd * cc.z + ad * k4.z;
        cn.w = fd * cc.w + ad * k4.w;
        O4[d * 32 + lane] = cn;
        #pragma unroll
        for (int off = 16; off; off >>= 1)
            part += __shfl_xor_sync(0xffffffffu, part, off);
        if (lane == 0) out_h[vo + d] = o_s[d] * part * inv;
    }
}

// ---------------------------------------------------------------------------
// Launch
// ---------------------------------------------------------------------------
extern "C" void kernel_launch(void* const* d_in, const int* in_sizes, int n_in,
                              void* d_out, int out_size)
{
    const float* x     = (const float*)d_in[0];
    const float* C     = (const float*)d_in[2];
    const float* n     = (const float*)d_in[3];
    const float* W_i   = (const float*)d_in[4];
    const float* b_i   = (const float*)d_in[5];
    const float* W_qkv = (const float*)d_in[6];
    const float* b_qkv = (const float*)d_in[7];

    float* out   = (float*)d_out;
    float* out_h = out;
    float* out_C = out + (size_t)BATCH * HID;
    float* out_n = out_C + (size_t)BATCH * NHEAD * HDIM * HDIM;

    cudaFuncSetAttribute(gates_mma_kernel,
                         cudaFuncAttributeMaxDynamicSharedMemorySize, G_DSMEM);
    cudaFuncSetAttribute(qkv_mma_kernel,
                         cudaFuncAttributeMaxDynamicSharedMemorySize, Q_DSMEM);

    split_x_kernel<<<(BATCH * HID) / 256, 256>>>(x);
    splitT_w_kernel<<<dim3(N3 / 32, HID / 32), 256>>>(W_i);
    splitT_wq_kernel<<<dim3(384 / 32, HDIM / 32, NHEAD), 256>>>(W_qkv);
    gates_mma_kernel<<<dim3(N3 / 96, BATCH / 128, 2), 256, G_DSMEM>>>();
    gates_epi_kernel<<<(BATCH * N3 / 4) / 256, 256>>>(b_i);
    qkv_mma_kernel<<<dim3(384 / 128, BATCH / 128, NHEAD), 256, Q_DSMEM>>>(b_qkv);
    state_kernel<<<BATCH * NHEAD, 128>>>(C, n, out_h, out_C, out_n);
}

// round 11
// speedup vs baseline: 1.2408x; 1.1147x over previous
#include <cuda_runtime.h>
#include <cuda_bf16.h>
#include <cstdint>
#include <math.h>

#define BATCH 256
#define NHEAD 16
#define HDIM  128
#define HID   2048        // NHEAD * HDIM
#define N3    6144        // 3 * HID

// Scratch: activated gates and projections, [B, HID] each
__device__ __align__(16) float g_i[BATCH * HID];
__device__ __align__(16) float g_f[BATCH * HID];
__device__ __align__(16) float g_o[BATCH * HID];
__device__ __align__(16) float g_q[BATCH * HID];
__device__ __align__(16) float g_k[BATCH * HID];
__device__ __align__(16) float g_v[BATCH * HID];

// Split-K partial accumulators for gates GEMM  [B, N3] each
__device__ __align__(16) float g_pa[(size_t)BATCH * N3];
__device__ __align__(16) float g_pb[(size_t)BATCH * N3];

// Split-precision scratch (bf16 hi/lo)
__device__ __align__(16) __nv_bfloat16 s_xh[BATCH * HID];
__device__ __align__(16) __nv_bfloat16 s_xl[BATCH * HID];
__device__ __align__(16) __nv_bfloat16 s_wh[(size_t)N3 * HID];   // W_i^T [6144,2048]
__device__ __align__(16) __nv_bfloat16 s_wl[(size_t)N3 * HID];
__device__ __align__(16) __nv_bfloat16 s_wqh[NHEAD * 384 * HDIM]; // W_qkv^T [h][384][128]
__device__ __align__(16) __nv_bfloat16 s_wql[NHEAD * 384 * HDIM];

// ---------------------------------------------------------------------------
// Split x -> bf16 hi/lo
// ---------------------------------------------------------------------------
__global__ __launch_bounds__(256) void split_x_kernel(const float* __restrict__ x)
{
    int idx = blockIdx.x * 256 + threadIdx.x;
    float v = x[idx];
    __nv_bfloat16 hi = __float2bfloat16(v);
    float lo = v - __bfloat162float(hi);
    s_xh[idx] = hi;
    s_xl[idx] = __float2bfloat16(lo);
}

// ---------------------------------------------------------------------------
// Split + transpose W_i [2048,6144] -> Wt hi/lo [6144,2048]
// ---------------------------------------------------------------------------
__global__ __launch_bounds__(256) void splitT_w_kernel(const float* __restrict__ W)
{
    __shared__ float tile[32][33];
    const int n0 = blockIdx.x * 32;
    const int k0 = blockIdx.y * 32;
    const int tx = threadIdx.x & 31;
    const int ty = threadIdx.x >> 5;   // 0..7

    #pragma unroll
    for (int j = 0; j < 4; j++)
        tile[ty + j * 8][tx] = W[(size_t)(k0 + ty + j * 8) * N3 + n0 + tx];
    __syncthreads();

    #pragma unroll
    for (int j = 0; j < 4; j++) {
        float v = tile[tx][ty + j * 8];
        __nv_bfloat16 hi = __float2bfloat16(v);
        float lo = v - __bfloat162float(hi);
        size_t o = (size_t)(n0 + ty + j * 8) * HID + k0 + tx;
        s_wh[o] = hi;
        s_wl[o] = __float2bfloat16(lo);
    }
}

// ---------------------------------------------------------------------------
// Split + transpose W_qkv [h][128][384] -> [h][384][128] hi/lo
// ---------------------------------------------------------------------------
__global__ __launch_bounds__(256) void splitT_wq_kernel(const float* __restrict__ Wq)
{
    __shared__ float tile[32][33];
    const int n0 = blockIdx.x * 32;     // 0..352
    const int k0 = blockIdx.y * 32;     // 0..96
    const int h  = blockIdx.z;
    const int tx = threadIdx.x & 31;
    const int ty = threadIdx.x >> 5;

    #pragma unroll
    for (int j = 0; j < 4; j++)
        tile[ty + j * 8][tx] = Wq[((size_t)h * HDIM + k0 + ty + j * 8) * 384 + n0 + tx];
    __syncthreads();

    #pragma unroll
    for (int j = 0; j < 4; j++) {
        float v = tile[tx][ty + j * 8];
        __nv_bfloat16 hi = __float2bfloat16(v);
        float lo = v - __bfloat162float(hi);
        size_t o = ((size_t)h * 384 + n0 + ty + j * 8) * HDIM + k0 + tx;
        s_wqh[o] = hi;
        s_wql[o] = __float2bfloat16(lo);
    }
}

// ---------------------------------------------------------------------------
// PTX helpers (sm_80-compatible: cp.async + ldmatrix + mma.sync)
// ---------------------------------------------------------------------------
__device__ __forceinline__ void cp_async16(uint32_t dst, const void* src) {
    asm volatile("cp.async.cg.shared.global [%0], [%1], 16;"
                 :: "r"(dst), "l"(src));
}
__device__ __forceinline__ void cp_commit() {
    asm volatile("cp.async.commit_group;");
}

__device__ __forceinline__ void ldm_x4(uint32_t* r, uint32_t addr) {
    asm volatile("ldmatrix.sync.aligned.m8n8.x4.shared.b16 {%0,%1,%2,%3}, [%4];"
                 : "=r"(r[0]), "=r"(r[1]), "=r"(r[2]), "=r"(r[3]) : "r"(addr));
}

__device__ __forceinline__ void mma16816(float* c, const uint32_t* a, const uint32_t* b) {
    asm volatile(
        "mma.sync.aligned.m16n8k16.row.col.f32.bf16.bf16.f32 "
        "{%0,%1,%2,%3}, {%4,%5,%6,%7}, {%8,%9}, {%0,%1,%2,%3};"
        : "+f"(c[0]), "+f"(c[1]), "+f"(c[2]), "+f"(c[3])
        : "r"(a[0]), "r"(a[1]), "r"(a[2]), "r"(a[3]), "r"(b[0]), "r"(b[1]));
}

// ===========================================================================
// Gates GEMM, merged-term + split-K=2:
//   D = Xh@Wh^T + Xl@Wh^T + Xh@Wl^T (bf16x3), all 3 terms per K-chunk.
// CTA tile 128x96, 256 threads, 8 warps 4Mx2N, warp tile 32x48.
// Per chunk (BK=64): stage xh, xl (128x128B) + wh, wl (96x128B), XOR-swizzled
// 128B rows (no pad). Ring 2 x 56KB = 112KB -> 2 CTAs/SM.
// Per ki per warp: 10 LDSM.x4 feed 36 MMAs (28.8 FLOP/smem-byte).
// ===========================================================================
#define XH_OFF 0
#define XL_OFF 16384
#define WH_OFF 32768
#define WL_OFF 45056
#define CH_STRIDE 57344           // 56KB per chunk buffer
#define G_DSMEM (2 * CH_STRIDE)   // 114688
#define G_NCHUNK 16               // per split-K half (32 total chunks of K=64)

__device__ __forceinline__ uint32_t swz(int row, int cu) {
    return (uint32_t)(row * 128 + ((cu ^ (row & 7)) << 4));
}

__global__ __launch_bounds__(256, 2) void gates_mma_kernel(void)
{
    extern __shared__ __nv_bfloat16 smem[];

    const int tid = threadIdx.x;
    const int lane = tid & 31;
    const int wid = tid >> 5;
    const int warp_m = (wid & 3) * 32;     // 0,32,64,96
    const int warp_n = (wid >> 2) * 48;    // 0,48
    const int n0 = blockIdx.x * 96;
    const int m0 = blockIdx.y * 128;
    const int zbase = blockIdx.z * G_NCHUNK;   // chunk offset (0 or 16)

    const int r_s = tid >> 3;              // 0..31
    const int seg = tid & 7;

    const uint32_t sbase = (uint32_t)__cvta_generic_to_shared(smem);

    float c[2][6][4];
    #pragma unroll
    for (int i = 0; i < 2; i++)
        #pragma unroll
        for (int j = 0; j < 6; j++)
            #pragma unroll
            for (int q = 0; q < 4; q++) c[i][j][q] = 0.0f;

    auto load_chunk = [&](int cc) {
        const int k0 = (zbase + cc) << 6;
        const uint32_t buf = sbase + (uint32_t)(cc & 1) * CH_STRIDE;
        #pragma unroll
        for (int h = 0; h < 4; h++) {
            const int row = r_s + h * 32;
            const uint32_t sw = swz(row, seg);
            cp_async16(buf + XH_OFF + sw,
                       s_xh + (size_t)(m0 + row) * HID + k0 + seg * 8);
            cp_async16(buf + XL_OFF + sw,
                       s_xl + (size_t)(m0 + row) * HID + k0 + seg * 8);
        }
        #pragma unroll
        for (int h = 0; h < 3; h++) {
            const int row = r_s + h * 32;
            const uint32_t sw = swz(row, seg);
            cp_async16(buf + WH_OFF + sw,
                       s_wh + (size_t)(n0 + row) * HID + k0 + seg * 8);
            cp_async16(buf + WL_OFF + sw,
                       s_wl + (size_t)(n0 + row) * HID + k0 + seg * 8);
        }
        cp_commit();
    };

    load_chunk(0);

    for (int cc = 0; cc < G_NCHUNK; ++cc) {
        asm volatile("cp.async.wait_group 0;");
        __syncthreads();
        if (cc + 1 < G_NCHUNK) load_chunk(cc + 1);

        const uint32_t buf = sbase + (uint32_t)(cc & 1) * CH_STRIDE;

        #pragma unroll
        for (int ki = 0; ki < 4; ki++) {
            const int kk = ki * 16;
            const int cub = kk >> 3;          // 16B-unit base within 128B row

            uint32_t axh[2][4], axl[2][4];
            #pragma unroll
            for (int slab = 0; slab < 2; slab++) {
                const int row = warp_m + slab * 16 + (lane & 15);
                const uint32_t off = swz(row, cub + (lane >> 4));
                ldm_x4(axh[slab], buf + XH_OFF + off);
                ldm_x4(axl[slab], buf + XL_OFF + off);
            }

            uint32_t bwh[6][2], bwl[6][2];
            const int g = lane >> 3;
            #pragma unroll
            for (int nb = 0; nb < 3; nb++) {
                const int nrow = warp_n + nb * 16 + ((g >> 1) << 3) + (lane & 7);
                const uint32_t off = swz(nrow, cub + (g & 1));
                uint32_t rr[4];
                ldm_x4(rr, buf + WH_OFF + off);
                bwh[nb * 2 + 0][0] = rr[0]; bwh[nb * 2 + 0][1] = rr[1];
                bwh[nb * 2 + 1][0] = rr[2]; bwh[nb * 2 + 1][1] = rr[3];
                uint32_t r2[4];
                ldm_x4(r2, buf + WL_OFF + off);
                bwl[nb * 2 + 0][0] = r2[0]; bwl[nb * 2 + 0][1] = r2[1];
                bwl[nb * 2 + 1][0] = r2[2]; bwl[nb * 2 + 1][1] = r2[3];
            }

            #pragma unroll
            for (int slab = 0; slab < 2; slab++)
                #pragma unroll
                for (int j = 0; j < 6; j++) {
                    mma16816(c[slab][j], axh[slab], bwh[j]);
                    mma16816(c[slab][j], axl[slab], bwh[j]);
                    mma16816(c[slab][j], axh[slab], bwl[j]);
                }
        }
    }

    // Store raw fp32 partials
    float* pout = (blockIdx.z == 0) ? g_pa : g_pb;
    #pragma unroll
    for (int slab = 0; slab < 2; slab++) {
        const int mrow = m0 + warp_m + slab * 16 + (lane >> 2);
        #pragma unroll
        for (int j = 0; j < 6; j++) {
            const int col = n0 + warp_n + j * 8 + ((lane & 3) << 1);
            *(float2*)(pout + (size_t)mrow * N3 + col) =
                make_float2(c[slab][j][0], c[slab][j][1]);
            *(float2*)(pout + (size_t)(mrow + 8) * N3 + col) =
                make_float2(c[slab][j][2], c[slab][j][3]);
        }
    }
}

// ---------------------------------------------------------------------------
// Gates epilogue: act(pa + pb + bias) -> g_i / g_f / g_o
// ---------------------------------------------------------------------------
__global__ __launch_bounds__(256) void gates_epi_kernel(const float* __restrict__ bias)
{
    const int idx4 = blockIdx.x * 256 + threadIdx.x;   // float4 index
    const int m = idx4 / (N3 / 4);
    const int col = (idx4 % (N3 / 4)) * 4;

    float4 a = *(const float4*)(g_pa + (size_t)m * N3 + col);
    float4 b = *(const float4*)(g_pb + (size_t)m * N3 + col);
    float4 bi = *(const float4*)(bias + col);

    float t0 = a.x + b.x + bi.x;
    float t1 = a.y + b.y + bi.y;
    float t2 = a.z + b.z + bi.z;
    float t3 = a.w + b.w + bi.w;

    const int cls = col >> 11;          // 0:i 1:f 2:o (float4 never straddles)
    float* outp = (cls == 0) ? g_i : ((cls == 1) ? g_f : g_o);
    float4 v;
    if (cls == 2) {
        v.x = 1.0f / (1.0f + expf(-t0));
        v.y = 1.0f / (1.0f + expf(-t1));
        v.z = 1.0f / (1.0f + expf(-t2));
        v.w = 1.0f / (1.0f + expf(-t3));
    } else {
        v.x = expf(t0); v.y = expf(t1); v.z = expf(t2); v.w = expf(t3);
    }
    *(float4*)(outp + (size_t)m * HID + (col & 2047)) = v;
}

// ===========================================================================
// QKV GEMM (per-head, bf16x3): M=256, N=384, K=128 per head.
// CTA tile 128x128, grid (3, 2, 16) = 96 CTAs, 6 stages of BK=64.
// ===========================================================================
#define SST 72                        // padded rows for qkv kernel (144B)
#define Q_STAGE (2 * 128 * SST * 2)   // 36864 (A + B, both 128 rows)
#define Q_NSTAGES 6
#define Q_DSMEM (3 * Q_STAGE)         // 110592

__global__ __launch_bounds__(256, 1) void qkv_mma_kernel(const float* __restrict__ bq)
{
    extern __shared__ __nv_bfloat16 smem[];

    const int tid = threadIdx.x;
    const int lane = tid & 31;
    const int wid = tid >> 5;
    const int warp_m = (wid & 3) * 32;
    const int warp_n = (wid >> 2) * 64;
    const int n0 = blockIdx.x * 128;       // 0,128,256 (of 384)
    const int m0 = blockIdx.y * 128;
    const int head = blockIdx.z;

    const int r_s = tid >> 3;
    const int seg = tid & 7;

    const uint32_t sbase = (uint32_t)__cvta_generic_to_shared(smem);

    float c[2][8][4];
    #pragma unroll
    for (int i = 0; i < 2; i++)
        #pragma unroll
        for (int j = 0; j < 8; j++)
            #pragma unroll
            for (int q = 0; q < 4; q++) c[i][j][q] = 0.0f;

    auto load_stage = [&](int s) {
        const int term = s >> 1;           // 0,1,2
        const int k0 = (s & 1) << 6;
        const __nv_bfloat16* Ap = (term == 1) ? s_xl : s_xh;
        const __nv_bfloat16* Bp = (term == 2) ? s_wql : s_wqh;
        const uint32_t buf = sbase + (uint32_t)(s % 3) * Q_STAGE;
        #pragma unroll
        for (int h = 0; h < 4; h++) {
            const int row = r_s + h * 32;
            const uint32_t doff = (uint32_t)(row * 144 + seg * 16);
            cp_async16(buf + doff,
                       Ap + (size_t)(m0 + row) * HID + head * HDIM + k0 + seg * 8);
            cp_async16(buf + (uint32_t)(128 * 144) + doff,
                       Bp + ((size_t)head * 384 + n0 + row) * HDIM + k0 + seg * 8);
        }
    };

    auto load_frags = [&](uint32_t Ab, uint32_t Bb, int kk,
                          uint32_t af[2][4], uint32_t bf[8][2]) {
        #pragma unroll
        for (int slab = 0; slab < 2; slab++) {
            const int row = warp_m + slab * 16 + (lane & 15);
            const int col = kk + ((lane >> 4) << 3);
            ldm_x4(af[slab], Ab + (uint32_t)(row * SST + col) * 2);
        }
        const int g = lane >> 3;
        #pragma unroll
        for (int nb = 0; nb < 4; nb++) {
            const int nrow = warp_n + nb * 16 + ((g >> 1) << 3) + (lane & 7);
            const int col = kk + ((g & 1) << 3);
            uint32_t rr[4];
            ldm_x4(rr, Bb + (uint32_t)(nrow * SST + col) * 2);
            bf[nb * 2 + 0][0] = rr[0]; bf[nb * 2 + 0][1] = rr[1];
            bf[nb * 2 + 1][0] = rr[2]; bf[nb * 2 + 1][1] = rr[3];
        }
    };

    load_stage(0); cp_commit();
    load_stage(1); cp_commit();

    uint32_t af[2][2][4];
    uint32_t bf[2][8][2];

    for (int s = 0; s < Q_NSTAGES; ++s) {
        asm volatile("cp.async.wait_group 1;");
        __syncthreads();
        if (s + 2 < Q_NSTAGES) load_stage(s + 2);
        cp_commit();

        const uint32_t Ab = sbase + (uint32_t)(s % 3) * Q_STAGE;
        const uint32_t Bb = Ab + (uint32_t)(128 * 144);

        load_frags(Ab, Bb, 0, af[0], bf[0]);
        #pragma unroll
        for (int ki = 0; ki < 4; ki++) {
            const int cur = ki & 1;
            if (ki < 3)
                load_frags(Ab, Bb, (ki + 1) * 16, af[cur ^ 1], bf[cur ^ 1]);
            #pragma unroll
            for (int slab = 0; slab < 2; slab++)
                #pragma unroll
                for (int j = 0; j < 8; j++)
                    mma16816(c[slab][j], af[cur][slab], bf[cur][j]);
        }
    }

    const float kscale = 0.08838834764831845f;   // 1/sqrt(128)

    #pragma unroll
    for (int slab = 0; slab < 2; slab++) {
        const int mrow = m0 + warp_m + slab * 16 + (lane >> 2);
        #pragma unroll
        for (int j = 0; j < 8; j++) {
            const int ncol = n0 + warp_n + j * 8 + ((lane & 3) << 1);  // 0..383
            const int cls = ncol >> 7;          // 0:q 1:k 2:v
            float* outp = (cls == 0) ? g_q : ((cls == 1) ? g_k : g_v);
            const int colb = ncol & 127;
            const float b0 = bq[head * 384 + ncol];
            const float b1 = bq[head * 384 + ncol + 1];
            float t0 = c[slab][j][0] + b0, t1 = c[slab][j][1] + b1;
            float t2 = c[slab][j][2] + b0, t3 = c[slab][j][3] + b1;
            if (cls == 1) { t0 *= kscale; t1 *= kscale; t2 *= kscale; t3 *= kscale; }
            *(float2*)(outp + (size_t)mrow * HID + head * HDIM + colb) =
                make_float2(t0, t1);
            *(float2*)(outp + (size_t)(mrow + 8) * HID + head * HDIM + colb) =
                make_float2(t2, t3);
        }
    }
}

// ---------------------------------------------------------------------------
// Fused state update (memory-roofline bound on C traffic)
// ---------------------------------------------------------------------------
__global__ __launch_bounds__(128) void state_kernel(
    const float* __restrict__ Cin, const float* __restrict__ nin,
    float* __restrict__ out_h, float* __restrict__ out_C,
    float* __restrict__ out_n)
{
    __shared__ float q_s[128], k_s[128];
    __shared__ float f_s[128], a_s[128], o_s[128];
    __shared__ float red[4];
    __shared__ float s_inv;

    const int t = threadIdx.x;
    const int w = t >> 5;
    const int lane = t & 31;
    const int vo = blockIdx.x * HDIM;

    float iv = g_i[vo + t], fv = g_f[vo + t], ov = g_o[vo + t];
    float qv = g_q[vo + t], kv = g_k[vo + t], vv = g_v[vo + t];
    float nv = nin[vo + t];

    float nn = fv * nv + iv * kv;
    out_n[vo + t] = nn;

    q_s[t] = qv; k_s[t] = kv;
    f_s[t] = fv; a_s[t] = iv * vv; o_s[t] = ov;

    float p = nn * qv;
    #pragma unroll
    for (int off = 16; off; off >>= 1) p += __shfl_xor_sync(0xffffffffu, p, off);
    if (lane == 0) red[w] = p;
    __syncthreads();
    if (t == 0) {
        float dot = red[0] + red[1] + red[2] + red[3];
        s_inv = 1.0f / fmaxf(fabsf(dot), 1.0f);
    }
    __syncthreads();
    const float inv = s_inv;

    const float4 q4 = ((const float4*)q_s)[lane];
    const float4 k4 = ((const float4*)k_s)[lane];
    const float4* C4 = (const float4*)(Cin + (size_t)blockIdx.x * HDIM * HDIM);
    float4* O4 = (float4*)(out_C + (size_t)blockIdx.x * HDIM * HDIM);

    #pragma unroll 4
    for (int r = 0; r < 32; r++) {
        const int d = (w << 5) + r;
        float4 cc = C4[d * 32 + lane];
        float part = cc.x * q4.x + cc.y * q4.y + cc.z * q4.z + cc.w * q4.w;
        const float fd = f_s[d], ad = a_s[d];
        float4 cn;
        cn.x = fd * cc.x + ad * k4.x;
        cn.y = fd * cc.y + ad * k4.y;
        cn.z = fd * cc.z + ad * k4.z;
        cn.w = fd * cc.w + ad * k4.w;
        O4[d * 32 + lane] = cn;
        #pragma unroll
        for (int off = 16; off; off >>= 1)
            part += __shfl_xor_sync(0xffffffffu, part, off);
        if (lane == 0) out_h[vo + d] = o_s[d] * part * inv;
    }
}

// ---------------------------------------------------------------------------
// Launch
// ---------------------------------------------------------------------------
extern "C" void kernel_launch(void* const* d_in, const int* in_sizes, int n_in,
                              void* d_out, int out_size)
{
    const float* x     = (const float*)d_in[0];
    const float* C     = (const float*)d_in[2];
    const float* n     = (const float*)d_in[3];
    const float* W_i   = (const float*)d_in[4];
    const float* b_i   = (const float*)d_in[5];
    const float* W_qkv = (const float*)d_in[6];
    const float* b_qkv = (const float*)d_in[7];

    float* out   = (float*)d_out;
    float* out_h = out;
    float* out_C = out + (size_t)BATCH * HID;
    float* out_n = out_C + (size_t)BATCH * NHEAD * HDIM * HDIM;

    cudaFuncSetAttribute(gates_mma_kernel,
                         cudaFuncAttributeMaxDynamicSharedMemorySize, G_DSMEM);
    cudaFuncSetAttribute(qkv_mma_kernel,
                         cudaFuncAttributeMaxDynamicSharedMemorySize, Q_DSMEM);

    split_x_kernel<<<(BATCH * HID) / 256, 256>>>(x);
    splitT_w_kernel<<<dim3(N3 / 32, HID / 32), 256>>>(W_i);
    splitT_wq_kernel<<<dim3(384 / 32, HDIM / 32, NHEAD), 256>>>(W_qkv);
    gates_mma_kernel<<<dim3(N3 / 96, BATCH / 128, 2), 256, G_DSMEM>>>();
    gates_epi_kernel<<<(BATCH * N3 / 4) / 256, 256>>>(b_i);
    qkv_mma_kernel<<<dim3(384 / 128, BATCH / 128, NHEAD), 256, Q_DSMEM>>>(b_qkv);
    state_kernel<<<BATCH * NHEAD, 128>>>(C, n, out_h, out_C, out_n);
}

// round 12
// speedup vs baseline: 1.3616x; 1.0973x over previous
#include <cuda_runtime.h>
#include <cuda_bf16.h>
#include <cstdint>
#include <math.h>

#define BATCH 256
#define NHEAD 16
#define HDIM  128
#define HID   2048        // NHEAD * HDIM
#define N3    6144        // 3 * HID

// qkv projections, [B, HID] each (b*HID + h*D + d)
__device__ __align__(16) float g_q[BATCH * HID];
__device__ __align__(16) float g_k[BATCH * HID];
__device__ __align__(16) float g_v[BATCH * HID];

// Split-K partial accumulators for gates GEMM  [B, N3] each
__device__ __align__(16) float g_pa[(size_t)BATCH * N3];
__device__ __align__(16) float g_pb[(size_t)BATCH * N3];

// Split-precision scratch (bf16 hi/lo)
__device__ __align__(16) __nv_bfloat16 s_xh[BATCH * HID];
__device__ __align__(16) __nv_bfloat16 s_xl[BATCH * HID];
__device__ __align__(16) __nv_bfloat16 s_wh[(size_t)N3 * HID];   // W_i^T [6144,2048]
__device__ __align__(16) __nv_bfloat16 s_wl[(size_t)N3 * HID];
__device__ __align__(16) __nv_bfloat16 s_wqh[NHEAD * 384 * HDIM]; // W_qkv^T [h][384][128]
__device__ __align__(16) __nv_bfloat16 s_wql[NHEAD * 384 * HDIM];

// ---------------------------------------------------------------------------
// PTX helpers
// ---------------------------------------------------------------------------
__device__ __forceinline__ void cp_async16(uint32_t dst, const void* src) {
    asm volatile("cp.async.cg.shared.global [%0], [%1], 16;"
                 :: "r"(dst), "l"(src));
}
__device__ __forceinline__ void cp_commit() {
    asm volatile("cp.async.commit_group;");
}

__device__ __forceinline__ void ldm_x4(uint32_t* r, uint32_t addr) {
    asm volatile("ldmatrix.sync.aligned.m8n8.x4.shared.b16 {%0,%1,%2,%3}, [%4];"
                 : "=r"(r[0]), "=r"(r[1]), "=r"(r[2]), "=r"(r[3]) : "r"(addr));
}

__device__ __forceinline__ void mma16816(float* c, const uint32_t* a, const uint32_t* b) {
    asm volatile(
        "mma.sync.aligned.m16n8k16.row.col.f32.bf16.bf16.f32 "
        "{%0,%1,%2,%3}, {%4,%5,%6,%7}, {%8,%9}, {%0,%1,%2,%3};"
        : "+f"(c[0]), "+f"(c[1]), "+f"(c[2]), "+f"(c[3])
        : "r"(a[0]), "r"(a[1]), "r"(a[2]), "r"(a[3]), "r"(b[0]), "r"(b[1]));
}

// ===========================================================================
// Unified prep kernel: splitT_w (12288 blocks) | splitT_wq (768) | split_x (2048)
// ===========================================================================
__global__ __launch_bounds__(256) void prep_kernel(
    const float* __restrict__ W, const float* __restrict__ Wq,
    const float* __restrict__ x)
{
    __shared__ float tile[32][33];
    const int bid = blockIdx.x;
    const int tx = threadIdx.x & 31;
    const int ty = threadIdx.x >> 5;   // 0..7

    if (bid < 12288) {
        // splitT_w: W_i [2048,6144] -> wh/wl [6144,2048]
        const int n0 = (bid % 192) * 32;
        const int k0 = (bid / 192) * 32;
        #pragma unroll
        for (int j = 0; j < 4; j++)
            tile[ty + j * 8][tx] = W[(size_t)(k0 + ty + j * 8) * N3 + n0 + tx];
        __syncthreads();
        #pragma unroll
        for (int j = 0; j < 4; j++) {
            float v = tile[tx][ty + j * 8];
            __nv_bfloat16 hi = __float2bfloat16(v);
            float lo = v - __bfloat162float(hi);
            size_t o = (size_t)(n0 + ty + j * 8) * HID + k0 + tx;
            s_wh[o] = hi;
            s_wl[o] = __float2bfloat16(lo);
        }
    } else if (bid < 13056) {
        // splitT_wq: W_qkv [h][128][384] -> [h][384][128]
        const int q = bid - 12288;
        const int n0 = (q % 12) * 32;
        const int k0 = ((q / 12) & 3) * 32;
        const int h  = q / 48;
        #pragma unroll
        for (int j = 0; j < 4; j++)
            tile[ty + j * 8][tx] = Wq[((size_t)h * HDIM + k0 + ty + j * 8) * 384 + n0 + tx];
        __syncthreads();
        #pragma unroll
        for (int j = 0; j < 4; j++) {
            float v = tile[tx][ty + j * 8];
            __nv_bfloat16 hi = __float2bfloat16(v);
            float lo = v - __bfloat162float(hi);
            size_t o = ((size_t)h * 384 + n0 + ty + j * 8) * HDIM + k0 + tx;
            s_wqh[o] = hi;
            s_wql[o] = __float2bfloat16(lo);
        }
    } else {
        // split_x
        const int idx = (bid - 13056) * 256 + threadIdx.x;
        float v = x[idx];
        __nv_bfloat16 hi = __float2bfloat16(v);
        float lo = v - __bfloat162float(hi);
        s_xh[idx] = hi;
        s_xl[idx] = __float2bfloat16(lo);
    }
}

// ===========================================================================
// Unified MMA kernel: blocks 0..255 = gates (merged-term, split-K=2),
// blocks 256..351 = qkv. Both validated mainloops unchanged.
// ===========================================================================
#define XH_OFF 0
#define XL_OFF 16384
#define WH_OFF 32768
#define WL_OFF 45056
#define CH_STRIDE 57344           // 56KB per chunk buffer
#define G_DSMEM (2 * CH_STRIDE)   // 114688
#define G_NCHUNK 16               // per split-K half

#define SST 72                        // padded rows for qkv path (144B)
#define Q_STAGE (2 * 128 * SST * 2)   // 36864
#define Q_NSTAGES 6

__device__ __forceinline__ uint32_t swz(int row, int cu) {
    return (uint32_t)(row * 128 + ((cu ^ (row & 7)) << 4));
}

__device__ void gates_body(int bid, __nv_bfloat16* smem)
{
    const int tid = threadIdx.x;
    const int lane = tid & 31;
    const int wid = tid >> 5;
    const int warp_m = (wid & 3) * 32;
    const int warp_n = (wid >> 2) * 48;
    const int n0 = (bid & 63) * 96;
    const int m0 = ((bid >> 6) & 1) * 128;
    const int bz = bid >> 7;
    const int zbase = bz * G_NCHUNK;

    const int r_s = tid >> 3;
    const int seg = tid & 7;

    const uint32_t sbase = (uint32_t)__cvta_generic_to_shared(smem);

    float c[2][6][4];
    #pragma unroll
    for (int i = 0; i < 2; i++)
        #pragma unroll
        for (int j = 0; j < 6; j++)
            #pragma unroll
            for (int q = 0; q < 4; q++) c[i][j][q] = 0.0f;

    auto load_chunk = [&](int cc) {
        const int k0 = (zbase + cc) << 6;
        const uint32_t buf = sbase + (uint32_t)(cc & 1) * CH_STRIDE;
        #pragma unroll
        for (int h = 0; h < 4; h++) {
            const int row = r_s + h * 32;
            const uint32_t sw = swz(row, seg);
            cp_async16(buf + XH_OFF + sw,
                       s_xh + (size_t)(m0 + row) * HID + k0 + seg * 8);
            cp_async16(buf + XL_OFF + sw,
                       s_xl + (size_t)(m0 + row) * HID + k0 + seg * 8);
        }
        #pragma unroll
        for (int h = 0; h < 3; h++) {
            const int row = r_s + h * 32;
            const uint32_t sw = swz(row, seg);
            cp_async16(buf + WH_OFF + sw,
                       s_wh + (size_t)(n0 + row) * HID + k0 + seg * 8);
            cp_async16(buf + WL_OFF + sw,
                       s_wl + (size_t)(n0 + row) * HID + k0 + seg * 8);
        }
        cp_commit();
    };

    load_chunk(0);

    for (int cc = 0; cc < G_NCHUNK; ++cc) {
        asm volatile("cp.async.wait_group 0;");
        __syncthreads();
        if (cc + 1 < G_NCHUNK) load_chunk(cc + 1);

        const uint32_t buf = sbase + (uint32_t)(cc & 1) * CH_STRIDE;

        #pragma unroll
        for (int ki = 0; ki < 4; ki++) {
            const int cub = ki * 2;

            uint32_t axh[2][4], axl[2][4];
            #pragma unroll
            for (int slab = 0; slab < 2; slab++) {
                const int row = warp_m + slab * 16 + (lane & 15);
                const uint32_t off = swz(row, cub + (lane >> 4));
                ldm_x4(axh[slab], buf + XH_OFF + off);
                ldm_x4(axl[slab], buf + XL_OFF + off);
            }

            uint32_t bwh[6][2], bwl[6][2];
            const int g = lane >> 3;
            #pragma unroll
            for (int nb = 0; nb < 3; nb++) {
                const int nrow = warp_n + nb * 16 + ((g >> 1) << 3) + (lane & 7);
                const uint32_t off = swz(nrow, cub + (g & 1));
                uint32_t rr[4];
                ldm_x4(rr, buf + WH_OFF + off);
                bwh[nb * 2 + 0][0] = rr[0]; bwh[nb * 2 + 0][1] = rr[1];
                bwh[nb * 2 + 1][0] = rr[2]; bwh[nb * 2 + 1][1] = rr[3];
                uint32_t r2[4];
                ldm_x4(r2, buf + WL_OFF + off);
                bwl[nb * 2 + 0][0] = r2[0]; bwl[nb * 2 + 0][1] = r2[1];
                bwl[nb * 2 + 1][0] = r2[2]; bwl[nb * 2 + 1][1] = r2[3];
            }

            #pragma unroll
            for (int slab = 0; slab < 2; slab++)
                #pragma unroll
                for (int j = 0; j < 6; j++) {
                    mma16816(c[slab][j], axh[slab], bwh[j]);
                    mma16816(c[slab][j], axl[slab], bwh[j]);
                    mma16816(c[slab][j], axh[slab], bwl[j]);
                }
        }
    }

    float* pout = (bz == 0) ? g_pa : g_pb;
    #pragma unroll
    for (int slab = 0; slab < 2; slab++) {
        const int mrow = m0 + warp_m + slab * 16 + (lane >> 2);
        #pragma unroll
        for (int j = 0; j < 6; j++) {
            const int col = n0 + warp_n + j * 8 + ((lane & 3) << 1);
            *(float2*)(pout + (size_t)mrow * N3 + col) =
                make_float2(c[slab][j][0], c[slab][j][1]);
            *(float2*)(pout + (size_t)(mrow + 8) * N3 + col) =
                make_float2(c[slab][j][2], c[slab][j][3]);
        }
    }
}

__device__ void qkv_body(int qb, __nv_bfloat16* smem, const float* __restrict__ bq)
{
    const int tid = threadIdx.x;
    const int lane = tid & 31;
    const int wid = tid >> 5;
    const int warp_m = (wid & 3) * 32;
    const int warp_n = (wid >> 2) * 64;
    const int n0 = (qb % 3) * 128;
    const int m0 = ((qb / 3) & 1) * 128;
    const int head = qb / 6;

    const int r_s = tid >> 3;
    const int seg = tid & 7;

    const uint32_t sbase = (uint32_t)__cvta_generic_to_shared(smem);

    float c[2][8][4];
    #pragma unroll
    for (int i = 0; i < 2; i++)
        #pragma unroll
        for (int j = 0; j < 8; j++)
            #pragma unroll
            for (int q = 0; q < 4; q++) c[i][j][q] = 0.0f;

    auto load_stage = [&](int s) {
        const int term = s >> 1;
        const int k0 = (s & 1) << 6;
        const __nv_bfloat16* Ap = (term == 1) ? s_xl : s_xh;
        const __nv_bfloat16* Bp = (term == 2) ? s_wql : s_wqh;
        const uint32_t buf = sbase + (uint32_t)(s % 3) * Q_STAGE;
        #pragma unroll
        for (int h = 0; h < 4; h++) {
            const int row = r_s + h * 32;
            const uint32_t doff = (uint32_t)(row * 144 + seg * 16);
            cp_async16(buf + doff,
                       Ap + (size_t)(m0 + row) * HID + head * HDIM + k0 + seg * 8);
            cp_async16(buf + (uint32_t)(128 * 144) + doff,
                       Bp + ((size_t)head * 384 + n0 + row) * HDIM + k0 + seg * 8);
        }
    };

    auto load_frags = [&](uint32_t Ab, uint32_t Bb, int kk,
                          uint32_t af[2][4], uint32_t bf[8][2]) {
        #pragma unroll
        for (int slab = 0; slab < 2; slab++) {
            const int row = warp_m + slab * 16 + (lane & 15);
            const int col = kk + ((lane >> 4) << 3);
            ldm_x4(af[slab], Ab + (uint32_t)(row * SST + col) * 2);
        }
        const int g = lane >> 3;
        #pragma unroll
        for (int nb = 0; nb < 4; nb++) {
            const int nrow = warp_n + nb * 16 + ((g >> 1) << 3) + (lane & 7);
            const int col = kk + ((g & 1) << 3);
            uint32_t rr[4];
            ldm_x4(rr, Bb + (uint32_t)(nrow * SST + col) * 2);
            bf[nb * 2 + 0][0] = rr[0]; bf[nb * 2 + 0][1] = rr[1];
            bf[nb * 2 + 1][0] = rr[2]; bf[nb * 2 + 1][1] = rr[3];
        }
    };

    load_stage(0); cp_commit();
    load_stage(1); cp_commit();

    uint32_t af[2][2][4];
    uint32_t bf[2][8][2];

    for (int s = 0; s < Q_NSTAGES; ++s) {
        asm volatile("cp.async.wait_group 1;");
        __syncthreads();
        if (s + 2 < Q_NSTAGES) load_stage(s + 2);
        cp_commit();

        const uint32_t Ab = sbase + (uint32_t)(s % 3) * Q_STAGE;
        const uint32_t Bb = Ab + (uint32_t)(128 * 144);

        load_frags(Ab, Bb, 0, af[0], bf[0]);
        #pragma unroll
        for (int ki = 0; ki < 4; ki++) {
            const int cur = ki & 1;
            if (ki < 3)
                load_frags(Ab, Bb, (ki + 1) * 16, af[cur ^ 1], bf[cur ^ 1]);
            #pragma unroll
            for (int slab = 0; slab < 2; slab++)
                #pragma unroll
                for (int j = 0; j < 8; j++)
                    mma16816(c[slab][j], af[cur][slab], bf[cur][j]);
        }
    }

    const float kscale = 0.08838834764831845f;   // 1/sqrt(128)

    #pragma unroll
    for (int slab = 0; slab < 2; slab++) {
        const int mrow = m0 + warp_m + slab * 16 + (lane >> 2);
        #pragma unroll
        for (int j = 0; j < 8; j++) {
            const int ncol = n0 + warp_n + j * 8 + ((lane & 3) << 1);
            const int cls = ncol >> 7;          // 0:q 1:k 2:v
            float* outp = (cls == 0) ? g_q : ((cls == 1) ? g_k : g_v);
            const int colb = ncol & 127;
            const float b0 = bq[head * 384 + ncol];
            const float b1 = bq[head * 384 + ncol + 1];
            float t0 = c[slab][j][0] + b0, t1 = c[slab][j][1] + b1;
            float t2 = c[slab][j][2] + b0, t3 = c[slab][j][3] + b1;
            if (cls == 1) { t0 *= kscale; t1 *= kscale; t2 *= kscale; t3 *= kscale; }
            *(float2*)(outp + (size_t)mrow * HID + head * HDIM + colb) =
                make_float2(t0, t1);
            *(float2*)(outp + (size_t)(mrow + 8) * HID + head * HDIM + colb) =
                make_float2(t2, t3);
        }
    }
}

__global__ __launch_bounds__(256, 2) void mma_kernel(const float* __restrict__ bq)
{
    extern __shared__ __nv_bfloat16 smem[];
    if (blockIdx.x < 256) gates_body(blockIdx.x, smem);
    else                  qkv_body(blockIdx.x - 256, smem, bq);
}

// ---------------------------------------------------------------------------
// Fused state update + gates epilogue. One block (128 thr) per (b,h).
// Gate activations computed inline from split-K partials.
// ---------------------------------------------------------------------------
__global__ __launch_bounds__(128) void state_kernel(
    const float* __restrict__ Cin, const float* __restrict__ nin,
    const float* __restrict__ bias,
    float* __restrict__ out_h, float* __restrict__ out_C,
    float* __restrict__ out_n)
{
    __shared__ float q_s[128], k_s[128];
    __shared__ float f_s[128], a_s[128], o_s[128];
    __shared__ float red[4];
    __shared__ float s_inv;

    const int t = threadIdx.x;
    const int w = t >> 5;
    const int lane = t & 31;
    const int vo = blockIdx.x * HDIM;

    // gates from partials: col = cls*2048 + hid, row b
    const size_t rowb = (size_t)(blockIdx.x >> 4) * N3;
    const int hid = ((blockIdx.x & 15) << 7) + t;

    float ti = g_pa[rowb + hid] + g_pb[rowb + hid] + bias[hid];
    float tf = g_pa[rowb + 2048 + hid] + g_pb[rowb + 2048 + hid] + bias[2048 + hid];
    float to = g_pa[rowb + 4096 + hid] + g_pb[rowb + 4096 + hid] + bias[4096 + hid];
    float iv = expf(ti);
    float fv = expf(tf);
    float ov = 1.0f / (1.0f + expf(-to));

    float qv = g_q[vo + t], kv = g_k[vo + t], vv = g_v[vo + t];
    float nv = nin[vo + t];

    float nn = fv * nv + iv * kv;
    out_n[vo + t] = nn;

    q_s[t] = qv; k_s[t] = kv;
    f_s[t] = fv; a_s[t] = iv * vv; o_s[t] = ov;

    float p = nn * qv;
    #pragma unroll
    for (int off = 16; off; off >>= 1) p += __shfl_xor_sync(0xffffffffu, p, off);
    if (lane == 0) red[w] = p;
    __syncthreads();
    if (t == 0) {
        float dot = red[0] + red[1] + red[2] + red[3];
        s_inv = 1.0f / fmaxf(fabsf(dot), 1.0f);
    }
    __syncthreads();
    const float inv = s_inv;

    const float4 q4 = ((const float4*)q_s)[lane];
    const float4 k4 = ((const float4*)k_s)[lane];
    const float4* C4 = (const float4*)(Cin + (size_t)blockIdx.x * HDIM * HDIM);
    float4* O4 = (float4*)(out_C + (size_t)blockIdx.x * HDIM * HDIM);

    #pragma unroll 4
    for (int r = 0; r < 32; r++) {
        const int d = (w << 5) + r;
        float4 cc = C4[d * 32 + lane];
        float part = cc.x * q4.x + cc.y * q4.y + cc.z * q4.z + cc.w * q4.w;
        const float fd = f_s[d], ad = a_s[d];
        float4 cn;
        cn.x = fd * cc.x + ad * k4.x;
        cn.y = fd * cc.y + ad * k4.y;
        cn.z = fd * cc.z + ad * k4.z;
        cn.w = fd * cc.w + ad * k4.w;
        O4[d * 32 + lane] = cn;
        #pragma unroll
        for (int off = 16; off; off >>= 1)
            part += __shfl_xor_sync(0xffffffffu, part, off);
        if (lane == 0) out_h[vo + d] = o_s[d] * part * inv;
    }
}

// ---------------------------------------------------------------------------
// Launch
// ---------------------------------------------------------------------------
extern "C" void kernel_launch(void* const* d_in, const int* in_sizes, int n_in,
                              void* d_out, int out_size)
{
    const float* x     = (const float*)d_in[0];
    const float* C     = (const float*)d_in[2];
    const float* n     = (const float*)d_in[3];
    const float* W_i   = (const float*)d_in[4];
    const float* b_i   = (const float*)d_in[5];
    const float* W_qkv = (const float*)d_in[6];
    const float* b_qkv = (const float*)d_in[7];

    float* out   = (float*)d_out;
    float* out_h = out;
    float* out_C = out + (size_t)BATCH * HID;
    float* out_n = out_C + (size_t)BATCH * NHEAD * HDIM * HDIM;

    cudaFuncSetAttribute(mma_kernel,
                         cudaFuncAttributeMaxDynamicSharedMemorySize, G_DSMEM);

    prep_kernel<<<15104, 256>>>(W_i, W_qkv, x);
    mma_kernel<<<352, 256, G_DSMEM>>>(b_qkv);
    state_kernel<<<BATCH * NHEAD, 128>>>(C, n, b_i, out_h, out_C, out_n);
}

// round 13
// speedup vs baseline: 1.3996x; 1.0279x over previous
#include <cuda_runtime.h>
#include <cuda_bf16.h>
#include <cstdint>
#include <math.h>

#define BATCH 256
#define NHEAD 16
#define HDIM  128
#define HID   2048        // NHEAD * HDIM
#define N3    6144        // 3 * HID

// qkv projections, [B, HID] each (b*HID + h*D + d)
__device__ __align__(16) float g_q[BATCH * HID];
__device__ __align__(16) float g_k[BATCH * HID];
__device__ __align__(16) float g_v[BATCH * HID];

// Split-K partial accumulators for gates GEMM  [B, N3] each
__device__ __align__(16) float g_pa[(size_t)BATCH * N3];
__device__ __align__(16) float g_pb[(size_t)BATCH * N3];

// Split-precision scratch (bf16 hi/lo)
__device__ __align__(16) __nv_bfloat16 s_xh[BATCH * HID];
__device__ __align__(16) __nv_bfloat16 s_xl[BATCH * HID];
__device__ __align__(16) __nv_bfloat16 s_wh[(size_t)N3 * HID];   // W_i^T [6144,2048]
__device__ __align__(16) __nv_bfloat16 s_wl[(size_t)N3 * HID];
__device__ __align__(16) __nv_bfloat16 s_wqh[NHEAD * 384 * HDIM]; // W_qkv^T [h][384][128]
__device__ __align__(16) __nv_bfloat16 s_wql[NHEAD * 384 * HDIM];

// ---------------------------------------------------------------------------
// PTX helpers
// ---------------------------------------------------------------------------
__device__ __forceinline__ void cp_async16(uint32_t dst, const void* src) {
    asm volatile("cp.async.cg.shared.global [%0], [%1], 16;"
                 :: "r"(dst), "l"(src));
}
__device__ __forceinline__ void cp_commit() {
    asm volatile("cp.async.commit_group;");
}

__device__ __forceinline__ void ldm_x4(uint32_t* r, uint32_t addr) {
    asm volatile("ldmatrix.sync.aligned.m8n8.x4.shared.b16 {%0,%1,%2,%3}, [%4];"
                 : "=r"(r[0]), "=r"(r[1]), "=r"(r[2]), "=r"(r[3]) : "r"(addr));
}

__device__ __forceinline__ void mma16816(float* c, const uint32_t* a, const uint32_t* b) {
    asm volatile(
        "mma.sync.aligned.m16n8k16.row.col.f32.bf16.bf16.f32 "
        "{%0,%1,%2,%3}, {%4,%5,%6,%7}, {%8,%9}, {%0,%1,%2,%3};"
        : "+f"(c[0]), "+f"(c[1]), "+f"(c[2]), "+f"(c[3])
        : "r"(a[0]), "r"(a[1]), "r"(a[2]), "r"(a[3]), "r"(b[0]), "r"(b[1]));
}

// ===========================================================================
// Unified prep kernel:
//   blocks [0, 3072)    : splitT_w, 64x64 tiles, bf16x2 packed stores
//   blocks [3072, 3840) : splitT_wq (32x32 tiles)
//   blocks [3840, 4352) : split_x (float4 in, uint2 out)
// ===========================================================================
__global__ __launch_bounds__(256) void prep_kernel(
    const float* __restrict__ W, const float* __restrict__ Wq,
    const float* __restrict__ x)
{
    __shared__ float tile[64][65];
    const int bid = blockIdx.x;
    const int t = threadIdx.x;

    if (bid < 3072) {
        // splitT_w: W_i [2048,6144] -> wh/wl [6144,2048], 64x64 tile
        const int n0 = (bid % 96) * 64;
        const int k0 = (bid / 96) * 64;
        const int nc = t & 63;
        const int kb = t >> 6;          // 0..3
        #pragma unroll
        for (int j = 0; j < 16; j++) {
            const int kr = kb + j * 4;
            tile[kr][nc] = W[(size_t)(k0 + kr) * N3 + n0 + nc];
        }
        __syncthreads();
        const int kp = t & 31;          // k pair 0..31
        const int nb = t >> 5;          // 0..7
        #pragma unroll
        for (int j = 0; j < 8; j++) {
            const int n = nb + j * 8;
            float v0 = tile[kp * 2][n];
            float v1 = tile[kp * 2 + 1][n];
            __nv_bfloat16 h0 = __float2bfloat16(v0);
            __nv_bfloat16 h1 = __float2bfloat16(v1);
            float l0 = v0 - __bfloat162float(h0);
            float l1 = v1 - __bfloat162float(h1);
            size_t o = (size_t)(n0 + n) * HID + k0 + kp * 2;
            __nv_bfloat162 H; H.x = h0; H.y = h1;
            __nv_bfloat162 L; L.x = __float2bfloat16(l0); L.y = __float2bfloat16(l1);
            *(__nv_bfloat162*)(s_wh + o) = H;
            *(__nv_bfloat162*)(s_wl + o) = L;
        }
    } else if (bid < 3840) {
        // splitT_wq: W_qkv [h][128][384] -> [h][384][128], 32x32 tile
        const int q = bid - 3072;
        const int n0 = (q % 12) * 32;
        const int k0 = ((q / 12) & 3) * 32;
        const int h  = q / 48;
        const int tx = t & 31;
        const int ty = t >> 5;
        #pragma unroll
        for (int j = 0; j < 4; j++)
            tile[ty + j * 8][tx] = Wq[((size_t)h * HDIM + k0 + ty + j * 8) * 384 + n0 + tx];
        __syncthreads();
        const int kp = t & 15;          // k pair 0..15
        const int nb = t >> 4;          // 0..15
        #pragma unroll
        for (int j = 0; j < 2; j++) {
            const int n = nb + j * 16;
            float v0 = tile[kp * 2][n];
            float v1 = tile[kp * 2 + 1][n];
            __nv_bfloat16 h0 = __float2bfloat16(v0);
            __nv_bfloat16 h1 = __float2bfloat16(v1);
            float l0 = v0 - __bfloat162float(h0);
            float l1 = v1 - __bfloat162float(h1);
            size_t o = ((size_t)h * 384 + n0 + n) * HDIM + k0 + kp * 2;
            __nv_bfloat162 H; H.x = h0; H.y = h1;
            __nv_bfloat162 L; L.x = __float2bfloat16(l0); L.y = __float2bfloat16(l1);
            *(__nv_bfloat162*)(s_wqh + o) = H;
            *(__nv_bfloat162*)(s_wql + o) = L;
        }
    } else {
        // split_x: float4 in, 2x bf16x2 out
        const int i4 = (bid - 3840) * 256 + t;     // float4 index
        float4 v = ((const float4*)x)[i4];
        __nv_bfloat16 h0 = __float2bfloat16(v.x);
        __nv_bfloat16 h1 = __float2bfloat16(v.y);
        __nv_bfloat16 h2 = __float2bfloat16(v.z);
        __nv_bfloat16 h3 = __float2bfloat16(v.w);
        __nv_bfloat162 H0; H0.x = h0; H0.y = h1;
        __nv_bfloat162 H1; H1.x = h2; H1.y = h3;
        __nv_bfloat162 L0, L1;
        L0.x = __float2bfloat16(v.x - __bfloat162float(h0));
        L0.y = __float2bfloat16(v.y - __bfloat162float(h1));
        L1.x = __float2bfloat16(v.z - __bfloat162float(h2));
        L1.y = __float2bfloat16(v.w - __bfloat162float(h3));
        ((__nv_bfloat162*)s_xh)[i4 * 2 + 0] = H0;
        ((__nv_bfloat162*)s_xh)[i4 * 2 + 1] = H1;
        ((__nv_bfloat162*)s_xl)[i4 * 2 + 0] = L0;
        ((__nv_bfloat162*)s_xl)[i4 * 2 + 1] = L1;
    }
}

// ===========================================================================
// Unified MMA kernel: blocks 0..255 = gates (merged-term, split-K=2),
// blocks 256..351 = qkv. Both validated mainloops unchanged (R11/R12).
// ===========================================================================
#define XH_OFF 0
#define XL_OFF 16384
#define WH_OFF 32768
#define WL_OFF 45056
#define CH_STRIDE 57344           // 56KB per chunk buffer
#define G_DSMEM (2 * CH_STRIDE)   // 114688
#define G_NCHUNK 16               // per split-K half

#define SST 72                        // padded rows for qkv path (144B)
#define Q_STAGE (2 * 128 * SST * 2)   // 36864
#define Q_NSTAGES 6

__device__ __forceinline__ uint32_t swz(int row, int cu) {
    return (uint32_t)(row * 128 + ((cu ^ (row & 7)) << 4));
}

__device__ void gates_body(int bid, __nv_bfloat16* smem)
{
    const int tid = threadIdx.x;
    const int lane = tid & 31;
    const int wid = tid >> 5;
    const int warp_m = (wid & 3) * 32;
    const int warp_n = (wid >> 2) * 48;
    const int n0 = (bid & 63) * 96;
    const int m0 = ((bid >> 6) & 1) * 128;
    const int bz = bid >> 7;
    const int zbase = bz * G_NCHUNK;

    const int r_s = tid >> 3;
    const int seg = tid & 7;

    const uint32_t sbase = (uint32_t)__cvta_generic_to_shared(smem);

    float c[2][6][4];
    #pragma unroll
    for (int i = 0; i < 2; i++)
        #pragma unroll
        for (int j = 0; j < 6; j++)
            #pragma unroll
            for (int q = 0; q < 4; q++) c[i][j][q] = 0.0f;

    auto load_chunk = [&](int cc) {
        const int k0 = (zbase + cc) << 6;
        const uint32_t buf = sbase + (uint32_t)(cc & 1) * CH_STRIDE;
        #pragma unroll
        for (int h = 0; h < 4; h++) {
            const int row = r_s + h * 32;
            const uint32_t sw = swz(row, seg);
            cp_async16(buf + XH_OFF + sw,
                       s_xh + (size_t)(m0 + row) * HID + k0 + seg * 8);
            cp_async16(buf + XL_OFF + sw,
                       s_xl + (size_t)(m0 + row) * HID + k0 + seg * 8);
        }
        #pragma unroll
        for (int h = 0; h < 3; h++) {
            const int row = r_s + h * 32;
            const uint32_t sw = swz(row, seg);
            cp_async16(buf + WH_OFF + sw,
                       s_wh + (size_t)(n0 + row) * HID + k0 + seg * 8);
            cp_async16(buf + WL_OFF + sw,
                       s_wl + (size_t)(n0 + row) * HID + k0 + seg * 8);
        }
        cp_commit();
    };

    load_chunk(0);

    for (int cc = 0; cc < G_NCHUNK; ++cc) {
        asm volatile("cp.async.wait_group 0;");
        __syncthreads();
        if (cc + 1 < G_NCHUNK) load_chunk(cc + 1);

        const uint32_t buf = sbase + (uint32_t)(cc & 1) * CH_STRIDE;

        #pragma unroll
        for (int ki = 0; ki < 4; ki++) {
            const int cub = ki * 2;

            uint32_t axh[2][4], axl[2][4];
            #pragma unroll
            for (int slab = 0; slab < 2; slab++) {
                const int row = warp_m + slab * 16 + (lane & 15);
                const uint32_t off = swz(row, cub + (lane >> 4));
                ldm_x4(axh[slab], buf + XH_OFF + off);
                ldm_x4(axl[slab], buf + XL_OFF + off);
            }

            uint32_t bwh[6][2], bwl[6][2];
            const int g = lane >> 3;
            #pragma unroll
            for (int nb = 0; nb < 3; nb++) {
                const int nrow = warp_n + nb * 16 + ((g >> 1) << 3) + (lane & 7);
                const uint32_t off = swz(nrow, cub + (g & 1));
                uint32_t rr[4];
                ldm_x4(rr, buf + WH_OFF + off);
                bwh[nb * 2 + 0][0] = rr[0]; bwh[nb * 2 + 0][1] = rr[1];
                bwh[nb * 2 + 1][0] = rr[2]; bwh[nb * 2 + 1][1] = rr[3];
                uint32_t r2[4];
                ldm_x4(r2, buf + WL_OFF + off);
                bwl[nb * 2 + 0][0] = r2[0]; bwl[nb * 2 + 0][1] = r2[1];
                bwl[nb * 2 + 1][0] = r2[2]; bwl[nb * 2 + 1][1] = r2[3];
            }

            #pragma unroll
            for (int slab = 0; slab < 2; slab++)
                #pragma unroll
                for (int j = 0; j < 6; j++) {
                    mma16816(c[slab][j], axh[slab], bwh[j]);
                    mma16816(c[slab][j], axl[slab], bwh[j]);
                    mma16816(c[slab][j], axh[slab], bwl[j]);
                }
        }
    }

    float* pout = (bz == 0) ? g_pa : g_pb;
    #pragma unroll
    for (int slab = 0; slab < 2; slab++) {
        const int mrow = m0 + warp_m + slab * 16 + (lane >> 2);
        #pragma unroll
        for (int j = 0; j < 6; j++) {
            const int col = n0 + warp_n + j * 8 + ((lane & 3) << 1);
            *(float2*)(pout + (size_t)mrow * N3 + col) =
                make_float2(c[slab][j][0], c[slab][j][1]);
            *(float2*)(pout + (size_t)(mrow + 8) * N3 + col) =
                make_float2(c[slab][j][2], c[slab][j][3]);
        }
    }
}

__device__ void qkv_body(int qb, __nv_bfloat16* smem, const float* __restrict__ bq)
{
    const int tid = threadIdx.x;
    const int lane = tid & 31;
    const int wid = tid >> 5;
    const int warp_m = (wid & 3) * 32;
    const int warp_n = (wid >> 2) * 64;
    const int n0 = (qb % 3) * 128;
    const int m0 = ((qb / 3) & 1) * 128;
    const int head = qb / 6;

    const int r_s = tid >> 3;
    const int seg = tid & 7;

    const uint32_t sbase = (uint32_t)__cvta_generic_to_shared(smem);

    float c[2][8][4];
    #pragma unroll
    for (int i = 0; i < 2; i++)
        #pragma unroll
        for (int j = 0; j < 8; j++)
            #pragma unroll
            for (int q = 0; q < 4; q++) c[i][j][q] = 0.0f;

    auto load_stage = [&](int s) {
        const int term = s >> 1;
        const int k0 = (s & 1) << 6;
        const __nv_bfloat16* Ap = (term == 1) ? s_xl : s_xh;
        const __nv_bfloat16* Bp = (term == 2) ? s_wql : s_wqh;
        const uint32_t buf = sbase + (uint32_t)(s % 3) * Q_STAGE;
        #pragma unroll
        for (int h = 0; h < 4; h++) {
            const int row = r_s + h * 32;
            const uint32_t doff = (uint32_t)(row * 144 + seg * 16);
            cp_async16(buf + doff,
                       Ap + (size_t)(m0 + row) * HID + head * HDIM + k0 + seg * 8);
            cp_async16(buf + (uint32_t)(128 * 144) + doff,
                       Bp + ((size_t)head * 384 + n0 + row) * HDIM + k0 + seg * 8);
        }
    };

    auto load_frags = [&](uint32_t Ab, uint32_t Bb, int kk,
                          uint32_t af[2][4], uint32_t bf[8][2]) {
        #pragma unroll
        for (int slab = 0; slab < 2; slab++) {
            const int row = warp_m + slab * 16 + (lane & 15);
            const int col = kk + ((lane >> 4) << 3);
            ldm_x4(af[slab], Ab + (uint32_t)(row * SST + col) * 2);
        }
        const int g = lane >> 3;
        #pragma unroll
        for (int nb = 0; nb < 4; nb++) {
            const int nrow = warp_n + nb * 16 + ((g >> 1) << 3) + (lane & 7);
            const int col = kk + ((g & 1) << 3);
            uint32_t rr[4];
            ldm_x4(rr, Bb + (uint32_t)(nrow * SST + col) * 2);
            bf[nb * 2 + 0][0] = rr[0]; bf[nb * 2 + 0][1] = rr[1];
            bf[nb * 2 + 1][0] = rr[2]; bf[nb * 2 + 1][1] = rr[3];
        }
    };

    load_stage(0); cp_commit();
    load_stage(1); cp_commit();

    uint32_t af[2][2][4];
    uint32_t bf[2][8][2];

    for (int s = 0; s < Q_NSTAGES; ++s) {
        asm volatile("cp.async.wait_group 1;");
        __syncthreads();
        if (s + 2 < Q_NSTAGES) load_stage(s + 2);
        cp_commit();

        const uint32_t Ab = sbase + (uint32_t)(s % 3) * Q_STAGE;
        const uint32_t Bb = Ab + (uint32_t)(128 * 144);

        load_frags(Ab, Bb, 0, af[0], bf[0]);
        #pragma unroll
        for (int ki = 0; ki < 4; ki++) {
            const int cur = ki & 1;
            if (ki < 3)
                load_frags(Ab, Bb, (ki + 1) * 16, af[cur ^ 1], bf[cur ^ 1]);
            #pragma unroll
            for (int slab = 0; slab < 2; slab++)
                #pragma unroll
                for (int j = 0; j < 8; j++)
                    mma16816(c[slab][j], af[cur][slab], bf[cur][j]);
        }
    }

    const float kscale = 0.08838834764831845f;   // 1/sqrt(128)

    #pragma unroll
    for (int slab = 0; slab < 2; slab++) {
        const int mrow = m0 + warp_m + slab * 16 + (lane >> 2);
        #pragma unroll
        for (int j = 0; j < 8; j++) {
            const int ncol = n0 + warp_n + j * 8 + ((lane & 3) << 1);
            const int cls = ncol >> 7;          // 0:q 1:k 2:v
            float* outp = (cls == 0) ? g_q : ((cls == 1) ? g_k : g_v);
            const int colb = ncol & 127;
            const float b0 = bq[head * 384 + ncol];
            const float b1 = bq[head * 384 + ncol + 1];
            float t0 = c[slab][j][0] + b0, t1 = c[slab][j][1] + b1;
            float t2 = c[slab][j][2] + b0, t3 = c[slab][j][3] + b1;
            if (cls == 1) { t0 *= kscale; t1 *= kscale; t2 *= kscale; t3 *= kscale; }
            *(float2*)(outp + (size_t)mrow * HID + head * HDIM + colb) =
                make_float2(t0, t1);
            *(float2*)(outp + (size_t)(mrow + 8) * HID + head * HDIM + colb) =
                make_float2(t2, t3);
        }
    }
}

__global__ __launch_bounds__(256, 2) void mma_kernel(const float* __restrict__ bq)
{
    extern __shared__ __nv_bfloat16 smem[];
    if (blockIdx.x < 256) gates_body(blockIdx.x, smem);
    else                  qkv_body(blockIdx.x - 256, smem, bq);
}

// ---------------------------------------------------------------------------
// Fused state update + gates epilogue. One block (128 thr) per (b,h).
// ---------------------------------------------------------------------------
__global__ __launch_bounds__(128) void state_kernel(
    const float* __restrict__ Cin, const float* __restrict__ nin,
    const float* __restrict__ bias,
    float* __restrict__ out_h, float* __restrict__ out_C,
    float* __restrict__ out_n)
{
    __shared__ float q_s[128], k_s[128];
    __shared__ float f_s[128], a_s[128], o_s[128];
    __shared__ float red[4];
    __shared__ float s_inv;

    const int t = threadIdx.x;
    const int w = t >> 5;
    const int lane = t & 31;
    const int vo = blockIdx.x * HDIM;

    const size_t rowb = (size_t)(blockIdx.x >> 4) * N3;
    const int hid = ((blockIdx.x & 15) << 7) + t;

    float ti = g_pa[rowb + hid] + g_pb[rowb + hid] + bias[hid];
    float tf = g_pa[rowb + 2048 + hid] + g_pb[rowb + 2048 + hid] + bias[2048 + hid];
    float to = g_pa[rowb + 4096 + hid] + g_pb[rowb + 4096 + hid] + bias[4096 + hid];
    float iv = expf(ti);
    float fv = expf(tf);
    float ov = 1.0f / (1.0f + expf(-to));

    float qv = g_q[vo + t], kv = g_k[vo + t], vv = g_v[vo + t];
    float nv = nin[vo + t];

    float nn = fv * nv + iv * kv;
    out_n[vo + t] = nn;

    q_s[t] = qv; k_s[t] = kv;
    f_s[t] = fv; a_s[t] = iv * vv; o_s[t] = ov;

    float p = nn * qv;
    #pragma unroll
    for (int off = 16; off; off >>= 1) p += __shfl_xor_sync(0xffffffffu, p, off);
    if (lane == 0) red[w] = p;
    __syncthreads();
    if (t == 0) {
        float dot = red[0] + red[1] + red[2] + red[3];
        s_inv = 1.0f / fmaxf(fabsf(dot), 1.0f);
    }
    __syncthreads();
    const float inv = s_inv;

    const float4 q4 = ((const float4*)q_s)[lane];
    const float4 k4 = ((const float4*)k_s)[lane];
    const float4* C4 = (const float4*)(Cin + (size_t)blockIdx.x * HDIM * HDIM);
    float4* O4 = (float4*)(out_C + (size_t)blockIdx.x * HDIM * HDIM);

    #pragma unroll 4
    for (int r = 0; r < 32; r++) {
        const int d = (w << 5) + r;
        float4 cc = C4[d * 32 + lane];
        float part = cc.x * q4.x + cc.y * q4.y + cc.z * q4.z + cc.w * q4.w;
        const float fd = f_s[d], ad = a_s[d];
        float4 cn;
        cn.x = fd * cc.x + ad * k4.x;
        cn.y = fd * cc.y + ad * k4.y;
        cn.z = fd * cc.z + ad * k4.z;
        cn.w = fd * cc.w + ad * k4.w;
        O4[d * 32 + lane] = cn;
        #pragma unroll
        for (int off = 16; off; off >>= 1)
            part += __shfl_xor_sync(0xffffffffu, part, off);
        if (lane == 0) out_h[vo + d] = o_s[d] * part * inv;
    }
}

// ---------------------------------------------------------------------------
// Launch
// ---------------------------------------------------------------------------
extern "C" void kernel_launch(void* const* d_in, const int* in_sizes, int n_in,
                              void* d_out, int out_size)
{
    const float* x     = (const float*)d_in[0];
    const float* C     = (const float*)d_in[2];
    const float* n     = (const float*)d_in[3];
    const float* W_i   = (const float*)d_in[4];
    const float* b_i   = (const float*)d_in[5];
    const float* W_qkv = (const float*)d_in[6];
    const float* b_qkv = (const float*)d_in[7];

    float* out   = (float*)d_out;
    float* out_h = out;
    float* out_C = out + (size_t)BATCH * HID;
    float* out_n = out_C + (size_t)BATCH * NHEAD * HDIM * HDIM;

    cudaFuncSetAttribute(mma_kernel,
                         cudaFuncAttributeMaxDynamicSharedMemorySize, G_DSMEM);

    prep_kernel<<<4352, 256>>>(W_i, W_qkv, x);
    mma_kernel<<<352, 256, G_DSMEM>>>(b_qkv);
    state_kernel<<<BATCH * NHEAD, 128>>>(C, n, b_i, out_h, out_C, out_n);
}